// round 2
// baseline (speedup 1.0000x reference)
#include <cuda_runtime.h>
#include <math.h>
#include <stdint.h>

#define NNODES 512
#define NEDGES 16384
#define LPN 20
#define TT 60
#define DD 128
#define H3 384
#define NGRU 21
#define GI_PER_G (NNODES*TT*H3)
#define LN_EPS 1e-5f

__device__ float g_GI[(size_t)NGRU * GI_PER_G];
__device__ float g_H[NGRU * NNODES * DD];
__device__ float g_cat[5 * NNODES * DD];
__device__ float g_bufA[NNODES * DD];
__device__ float g_bufB[NNODES * DD];
__device__ float g_bufC[NNODES * DD];
__device__ int   g_deg[NNODES];
__device__ float g_dinv[NNODES];
__device__ float g_logits[NNODES * 2];

__device__ __forceinline__ float sigm(float x) { return 1.f / (1.f + expf(-x)); }

// Phase 1: gi = x @ Wih^T + bih, all 21 GRUs. grid (240,3,21), 256 thr, 128KB smem
__global__ __launch_bounds__(256) void gi_gemm_kernel(
    const float* __restrict__ x_lp, const float* __restrict__ x_ns,
    const float* __restrict__ Wih_lp, const float* __restrict__ bih_lp,
    const float* __restrict__ Wih_ns, const float* __restrict__ bih_ns)
{
    extern __shared__ float sm[];
    float* As = sm;
    float* Bs = sm + 128 * 128;
    const int g = blockIdx.z;
    const int mbase = blockIdx.x * 128;
    const int nbase = blockIdx.y * 128;
    const int tid = threadIdx.x;

    const float* W  = (g < LPN) ? (Wih_lp + (size_t)g * H3 * DD) : Wih_ns;
    const float* bi = (g < LPN) ? (bih_lp + g * H3) : bih_ns;
    const float* xp = (g < LPN) ? x_lp : x_ns;

    #pragma unroll
    for (int it = 0; it < 16; it++) {
        int f = tid + it * 256;
        int r = f >> 5, c4 = f & 31;
        int row = mbase + r;
        size_t off;
        if (g < LPN) {
            int n = row / TT, t = row - n * TT;
            off = (size_t)n * (LPN * TT * DD) + (size_t)g * (TT * DD) + (size_t)t * DD;
        } else off = (size_t)row * DD;
        *reinterpret_cast<float4*>(As + r * 128 + c4 * 4) =
            *reinterpret_cast<const float4*>(xp + off + c4 * 4);
    }
    #pragma unroll
    for (int it = 0; it < 16; it++) {
        int f = tid + it * 256;
        int j = f >> 5, c4 = f & 31;
        *reinterpret_cast<float4*>(Bs + j * 128 + c4 * 4) =
            *reinterpret_cast<const float4*>(W + (size_t)(nbase + j) * DD + c4 * 4);
    }
    __syncthreads();

    const int ty = tid >> 4, tx = tid & 15, lane = tid & 31;
    float acc[8][8];
    #pragma unroll
    for (int i = 0; i < 8; i++)
        #pragma unroll
        for (int j = 0; j < 8; j++) acc[i][j] = 0.f;

    #pragma unroll 2
    for (int k = 0; k < 128; k++) {
        int kk = k + lane; if (kk >= 128) kk -= 128;
        float a[8], b[8];
        #pragma unroll
        for (int i = 0; i < 8; i++) a[i] = As[(ty * 8 + i) * 128 + kk];
        #pragma unroll
        for (int j = 0; j < 8; j++) b[j] = Bs[(tx * 8 + j) * 128 + kk];
        #pragma unroll
        for (int i = 0; i < 8; i++)
            #pragma unroll
            for (int j = 0; j < 8; j++) acc[i][j] += a[i] * b[j];
    }

    float bcol[8];
    #pragma unroll
    for (int j = 0; j < 8; j++) bcol[j] = bi[nbase + tx * 8 + j];
    float* outp = g_GI + (size_t)g * GI_PER_G;
    #pragma unroll
    for (int i = 0; i < 8; i++) {
        float* rp = outp + (size_t)(mbase + ty * 8 + i) * H3 + nbase + tx * 8;
        *reinterpret_cast<float4*>(rp) = make_float4(
            acc[i][0]+bcol[0], acc[i][1]+bcol[1], acc[i][2]+bcol[2], acc[i][3]+bcol[3]);
        *reinterpret_cast<float4*>(rp+4) = make_float4(
            acc[i][4]+bcol[4], acc[i][5]+bcol[5], acc[i][6]+bcol[6], acc[i][7]+bcol[7]);
    }
}

// Phase 2: recurrence. grid (13,21), 256 thr, smem = 384*128*4 + 40*128*4
__global__ __launch_bounds__(256) void gru_rec_kernel(
    const float* __restrict__ Whh_lp, const float* __restrict__ bhh_lp,
    const float* __restrict__ Whh_ns, const float* __restrict__ bhh_ns)
{
    extern __shared__ float sm[];
    float* ws = sm;
    float* hs = sm + H3 * DD;
    const int g = blockIdx.y;
    const int base = blockIdx.x * 40;
    const int cnt = min(40, NNODES - base);
    const int tid = threadIdx.x;

    const float* W  = (g < LPN) ? (Whh_lp + (size_t)g * H3 * DD) : Whh_ns;
    const float* bh = (g < LPN) ? (bhh_lp + g * H3) : bhh_ns;

    const float4* W4 = reinterpret_cast<const float4*>(W);
    float4* ws4 = reinterpret_cast<float4*>(ws);
    for (int f = tid; f < H3 * DD / 4; f += 256) ws4[f] = W4[f];
    for (int f = tid; f < 40 * DD; f += 256) hs[f] = 0.f;

    const int ng = tid >> 5, dg = tid & 31;
    float bias[3][4];
    #pragma unroll
    for (int gg = 0; gg < 3; gg++)
        #pragma unroll
        for (int b = 0; b < 4; b++) bias[gg][b] = bh[gg * 128 + dg * 4 + b];
    __syncthreads();

    const float4* gi4 = reinterpret_cast<const float4*>(g_GI + (size_t)g * GI_PER_G);

    for (int t = 0; t < TT; t++) {
        float acc[3][4][5];
        #pragma unroll
        for (int gg = 0; gg < 3; gg++)
            #pragma unroll
            for (int b = 0; b < 4; b++)
                #pragma unroll
                for (int a = 0; a < 5; a++) acc[gg][b][a] = 0.f;

        #pragma unroll 2
        for (int k = 0; k < 128; k++) {
            int kk = k + dg; if (kk >= 128) kk -= 128;
            float hv[5];
            #pragma unroll
            for (int a = 0; a < 5; a++) hv[a] = hs[(ng + 8 * a) * 128 + kk];
            #pragma unroll
            for (int gg = 0; gg < 3; gg++)
                #pragma unroll
                for (int b = 0; b < 4; b++) {
                    float w = ws[(gg * 128 + dg * 4 + b) * 128 + kk];
                    #pragma unroll
                    for (int a = 0; a < 5; a++) acc[gg][b][a] += w * hv[a];
                }
        }
        __syncthreads();

        #pragma unroll
        for (int a = 0; a < 5; a++) {
            int nl = ng + 8 * a;
            if (nl < cnt) {
                int n = base + nl;
                size_t rb4 = ((size_t)n * TT + t) * (H3 / 4);
                float4 gr = gi4[rb4 + dg];
                float4 gz = gi4[rb4 + 32 + dg];
                float4 gn = gi4[rb4 + 64 + dg];
                float ir[4]  = {gr.x, gr.y, gr.z, gr.w};
                float iz[4]  = {gz.x, gz.y, gz.z, gz.w};
                float inn[4] = {gn.x, gn.y, gn.z, gn.w};
                float* hrow = hs + nl * 128 + dg * 4;
                #pragma unroll
                for (int b = 0; b < 4; b++) {
                    float r = sigm(ir[b] + acc[0][b][a] + bias[0][b]);
                    float z = sigm(iz[b] + acc[1][b][a] + bias[1][b]);
                    float nn = tanhf(inn[b] + r * (acc[2][b][a] + bias[2][b]));
                    hrow[b] = (1.f - z) * nn + z * hrow[b];
                }
            }
        }
        __syncthreads();
    }
    float* Hout = g_H + (size_t)g * NNODES * DD + (size_t)base * DD;
    for (int f = tid; f < cnt * DD; f += 256) Hout[f] = hs[f];
}

// C[m][n] = sum_k A[m][k]*B[n][k] (+bias). grid (M/32, ceil(N/32)), 256 thr
__global__ void gemm_tn_kernel(const float* __restrict__ A, int lda,
                               const float* __restrict__ B, int ldb,
                               const float* __restrict__ bias,
                               float* __restrict__ C, int ldc,
                               int M, int N, int K)
{
    __shared__ float As[32 * 32];
    __shared__ float Bs[32 * 33];
    const int rbase = blockIdx.x * 32;
    const int cbase = blockIdx.y * 32;
    const int tid = threadIdx.x;
    const int ty = tid >> 5, tx = tid & 31;

    float acc[4] = {0.f, 0.f, 0.f, 0.f};
    for (int kb = 0; kb < K; kb += 32) {
        #pragma unroll
        for (int i = 0; i < 4; i++) {
            int idx = tid + i * 256;
            int r = idx >> 5, kk = idx & 31;
            As[r * 32 + kk] = A[(size_t)(rbase + r) * lda + kb + kk];
            Bs[r * 33 + kk] = (cbase + r < N) ? B[(size_t)(cbase + r) * ldb + kb + kk] : 0.f;
        }
        __syncthreads();
        #pragma unroll
        for (int kk = 0; kk < 32; kk++) {
            float bv = Bs[tx * 33 + kk];
            #pragma unroll
            for (int i = 0; i < 4; i++)
                acc[i] += As[(ty + 8 * i) * 32 + kk] * bv;
        }
        __syncthreads();
    }
    if (cbase + tx < N) {
        float bb = bias ? bias[cbase + tx] : 0.f;
        #pragma unroll
        for (int i = 0; i < 4; i++)
            C[(size_t)(rbase + ty + 8 * i) * ldc + cbase + tx] = acc[i] + bb;
    }
}

__global__ void build_cat_kernel(const float* __restrict__ x_pdt,
                                 const float* __restrict__ x_ref,
                                 const float* __restrict__ x_def)
{
    int i = blockIdx.x * 256 + threadIdx.x;
    g_cat[i] = x_pdt[i];
    g_cat[NNODES * DD + i] = x_ref[i];
    g_cat[2 * NNODES * DD + i] = x_def[i];
    g_cat[4 * NNODES * DD + i] = g_H[(size_t)LPN * NNODES * DD + i];
}

__global__ void deg_init_kernel() {
    int i = blockIdx.x * 256 + threadIdx.x;
    if (i < NNODES) g_deg[i] = 1;
}
__global__ void deg_edge_kernel(const int* __restrict__ ei) {
    int e = blockIdx.x * 256 + threadIdx.x;
    if (e < NEDGES) atomicAdd(&g_deg[ei[NEDGES + e]], 1);
}
__global__ void dinv_kernel() {
    int i = blockIdx.x * 256 + threadIdx.x;
    if (i < NNODES) g_dinv[i] = rsqrtf((float)g_deg[i]);
}
__global__ void agg_init_kernel(const float* __restrict__ xw,
                                const float* __restrict__ bias,
                                float* __restrict__ out)
{
    int i = blockIdx.x * 256 + threadIdx.x;
    int n = i >> 7, d = i & 127;
    float di = g_dinv[n];
    out[i] = bias[d] + di * di * xw[i];
}
__global__ void agg_edge_kernel(const float* __restrict__ xw,
                                const int* __restrict__ ei,
                                float* __restrict__ out)
{
    int i = blockIdx.x * 256 + threadIdx.x;
    int e = i >> 7, d = i & 127;
    int s = ei[e], t = ei[NEDGES + e];
    atomicAdd(&out[t * 128 + d], xw[s * 128 + d] * g_dinv[s] * g_dinv[t]);
}
__global__ void relu_ln_kernel(const float* __restrict__ in,
                               const float* __restrict__ gam,
                               const float* __restrict__ bet,
                               float* __restrict__ out)
{
    int row = blockIdx.x, d = threadIdx.x;
    float v = fmaxf(in[row * 128 + d], 0.f);
    float s = v, sq = v * v;
    #pragma unroll
    for (int o = 16; o > 0; o >>= 1) {
        s  += __shfl_xor_sync(0xffffffffu, s, o);
        sq += __shfl_xor_sync(0xffffffffu, sq, o);
    }
    __shared__ float ss[4], ssq[4];
    int w = d >> 5, l = d & 31;
    if (l == 0) { ss[w] = s; ssq[w] = sq; }
    __syncthreads();
    float st = ss[0] + ss[1] + ss[2] + ss[3];
    float sqt = ssq[0] + ssq[1] + ssq[2] + ssq[3];
    float m = st * (1.f / 128.f);
    float var = sqt * (1.f / 128.f) - m * m;
    out[row * 128 + d] = (v - m) * rsqrtf(var + LN_EPS) * gam[d] + bet[d];
}
__global__ void relu_kernel(const float* __restrict__ in, float* __restrict__ out) {
    int i = blockIdx.x * 256 + threadIdx.x;
    if (i < NNODES * DD) out[i] = fmaxf(in[i], 0.f);
}
__global__ void logsoftmax_kernel(float* __restrict__ out) {
    int i = blockIdx.x * 256 + threadIdx.x;
    if (i < NNODES) {
        float a = g_logits[2 * i], b = g_logits[2 * i + 1];
        float m = fmaxf(a, b);
        float lse = m + logf(expf(a - m) + expf(b - m));
        out[2 * i] = a - lse;
        out[2 * i + 1] = b - lse;
    }
}

extern "C" void kernel_launch(void* const* d_in, const int* in_sizes, int n_in,
                              void* d_out, int out_size)
{
    const float* x_lp    = (const float*)d_in[0];
    const float* x_ns    = (const float*)d_in[1];
    const float* x_ref   = (const float*)d_in[2];
    const float* x_def   = (const float*)d_in[3];
    const float* x_pdt   = (const float*)d_in[4];
    const int*   edge    = (const int*)  d_in[5];
    const float* Wih_lp  = (const float*)d_in[6];
    const float* Whh_lp  = (const float*)d_in[7];
    const float* bih_lp  = (const float*)d_in[8];
    const float* bhh_lp  = (const float*)d_in[9];
    const float* lp_fc_W = (const float*)d_in[10];
    const float* lp_fc_b = (const float*)d_in[11];
    const float* Wih_ns  = (const float*)d_in[12];
    const float* Whh_ns  = (const float*)d_in[13];
    const float* bih_ns  = (const float*)d_in[14];
    const float* bhh_ns  = (const float*)d_in[15];
    const float* all_fc_W = (const float*)d_in[16];
    const float* all_fc_b = (const float*)d_in[17];
    const float* convW[3] = {(const float*)d_in[18], (const float*)d_in[20], (const float*)d_in[22]};
    const float* convB[3] = {(const float*)d_in[19], (const float*)d_in[21], (const float*)d_in[23]};
    const float* lnG[2] = {(const float*)d_in[24], (const float*)d_in[26]};
    const float* lnB[2] = {(const float*)d_in[25], (const float*)d_in[27]};
    const float* mp1_W = (const float*)d_in[28];
    const float* mp1_b = (const float*)d_in[29];
    const float* mp2_W = (const float*)d_in[30];
    const float* mp2_b = (const float*)d_in[31];
    float* out = (float*)d_out;
    (void)in_sizes; (void)n_in; (void)out_size;

    float *H, *cat, *bufA, *bufB, *bufC, *logits;
    cudaGetSymbolAddress((void**)&H, g_H);
    cudaGetSymbolAddress((void**)&cat, g_cat);
    cudaGetSymbolAddress((void**)&bufA, g_bufA);
    cudaGetSymbolAddress((void**)&bufB, g_bufB);
    cudaGetSymbolAddress((void**)&bufC, g_bufC);
    cudaGetSymbolAddress((void**)&logits, g_logits);

    cudaFuncSetAttribute(gi_gemm_kernel, cudaFuncAttributeMaxDynamicSharedMemorySize, 131072);
    cudaFuncSetAttribute(gru_rec_kernel, cudaFuncAttributeMaxDynamicSharedMemorySize, 217088);

    gi_gemm_kernel<<<dim3(240, 3, NGRU), 256, 131072>>>(x_lp, x_ns, Wih_lp, bih_lp, Wih_ns, bih_ns);
    gru_rec_kernel<<<dim3(13, NGRU), 256, 217088>>>(Whh_lp, bhh_lp, Whh_ns, bhh_ns);

    // lp_fc: [512, 2560] @ lp_fc_W^T -> cat segment 3
    gemm_tn_kernel<<<dim3(16, 4), 256>>>(H, LPN * DD, lp_fc_W, LPN * DD, lp_fc_b,
                                         cat + 3 * NNODES * DD, DD, NNODES, DD, LPN * DD);
    build_cat_kernel<<<256, 256>>>(x_pdt, x_ref, x_def);
    // all_fc: [512, 640] -> bufA
    gemm_tn_kernel<<<dim3(16, 4), 256>>>(cat, 5 * DD, all_fc_W, 5 * DD, all_fc_b,
                                         bufA, DD, NNODES, DD, 5 * DD);

    deg_init_kernel<<<2, 256>>>();
    deg_edge_kernel<<<NEDGES / 256, 256>>>(edge);
    dinv_kernel<<<2, 256>>>();

    // conv0
    gemm_tn_kernel<<<dim3(16, 4), 256>>>(bufA, DD, convW[0], DD, nullptr, bufB, DD, NNODES, DD, DD);
    agg_init_kernel<<<256, 256>>>(bufB, convB[0], bufC);
    agg_edge_kernel<<<NEDGES * DD / 256, 256>>>(bufB, edge, bufC);
    relu_ln_kernel<<<NNODES, 128>>>(bufC, lnG[0], lnB[0], bufA);
    // conv1
    gemm_tn_kernel<<<dim3(16, 4), 256>>>(bufA, DD, convW[1], DD, nullptr, bufB, DD, NNODES, DD, DD);
    agg_init_kernel<<<256, 256>>>(bufB, convB[1], bufC);
    agg_edge_kernel<<<NEDGES * DD / 256, 256>>>(bufB, edge, bufC);
    relu_ln_kernel<<<NNODES, 128>>>(bufC, lnG[1], lnB[1], bufA);
    // conv2 -> emb goes straight to d_out[0:65536]
    gemm_tn_kernel<<<dim3(16, 4), 256>>>(bufA, DD, convW[2], DD, nullptr, bufB, DD, NNODES, DD, DD);
    agg_init_kernel<<<256, 256>>>(bufB, convB[2], out);
    agg_edge_kernel<<<NEDGES * DD / 256, 256>>>(bufB, edge, out);
    relu_kernel<<<256, 256>>>(out, bufA);
    // mp1, mp2
    gemm_tn_kernel<<<dim3(16, 4), 256>>>(bufA, DD, mp1_W, DD, mp1_b, bufB, DD, NNODES, DD, DD);
    gemm_tn_kernel<<<dim3(16, 1), 256>>>(bufB, DD, mp2_W, DD, mp2_b, logits, 2, NNODES, 2, DD);
    logsoftmax_kernel<<<2, 256>>>(out + NNODES * DD);
}

// round 4
// speedup vs baseline: 1.1548x; 1.1548x over previous
#include <cuda_runtime.h>
#include <math.h>
#include <stdint.h>

#define NNODES 512
#define NEDGES 16384
#define LPN 20
#define TT 60
#define DD 128
#define H3 384
#define NGRU 21
#define GI_PER_G (NNODES*TT*H3)
#define LN_EPS 1e-5f

__device__ float g_GI[(size_t)NGRU * GI_PER_G];
__device__ float g_H[NGRU * NNODES * DD];
__device__ float g_cat[5 * NNODES * DD];
__device__ float g_bufA[NNODES * DD];
__device__ float g_bufB[NNODES * DD];
__device__ float g_bufC[NNODES * DD];
__device__ int   g_deg[NNODES];
__device__ float g_dinv[NNODES];
__device__ float g_logits[NNODES * 2];

__device__ __forceinline__ float sigm(float x) { return 1.f / (1.f + expf(-x)); }

__device__ __forceinline__ uint32_t f2tf32(float a) {
    uint32_t r;
    asm("cvt.rna.tf32.f32 %0, %1;" : "=r"(r) : "f"(a));
    return r;
}
__device__ __forceinline__ void mma_tf32(float& d0, float& d1, float& d2, float& d3,
                                         uint32_t a0, uint32_t a1, uint32_t a2, uint32_t a3,
                                         uint32_t b0, uint32_t b1) {
    asm volatile("mma.sync.aligned.m16n8k8.row.col.f32.tf32.tf32.f32 "
                 "{%0,%1,%2,%3}, {%4,%5,%6,%7}, {%8,%9}, {%0,%1,%2,%3};"
                 : "+f"(d0), "+f"(d1), "+f"(d2), "+f"(d3)
                 : "r"(a0), "r"(a1), "r"(a2), "r"(a3), "r"(b0), "r"(b1));
}

// Phase 1 (tensor): gi = x @ Wih^T + bih via tf32x3 split mma.
// grid (240, 3, 21), 256 thr (8 warps, 2m x 4n), dyn smem = 3 * 128*132*4
#define APAD 132
__global__ __launch_bounds__(256) void gi_mma_kernel(
    const float* __restrict__ x_lp, const float* __restrict__ x_ns,
    const float* __restrict__ Wih_lp, const float* __restrict__ bih_lp,
    const float* __restrict__ Wih_ns, const float* __restrict__ bih_ns)
{
    extern __shared__ float sm[];
    float* As  = sm;                     // [128][132] fp32
    float* Bhi = sm + 128 * APAD;        // [128][132] tf32 hi (n-major, k cols)
    float* Blo = sm + 2 * 128 * APAD;    // [128][132] tf32 lo
    const int g = blockIdx.z;
    const int mbase = blockIdx.x * 128;
    const int nbase = blockIdx.y * 128;
    const int tid = threadIdx.x;

    const float* W  = (g < LPN) ? (Wih_lp + (size_t)g * H3 * DD) : Wih_ns;
    const float* bi = (g < LPN) ? (bih_lp + g * H3) : bih_ns;
    const float* xp = (g < LPN) ? x_lp : x_ns;

    // load A tile (fp32)
    #pragma unroll
    for (int it = 0; it < 16; it++) {
        int f = tid + it * 256;
        int r = f >> 5, c4 = f & 31;
        int row = mbase + r;
        size_t off;
        if (g < LPN) {
            int n = row / TT, t = row - n * TT;
            off = (size_t)n * (LPN * TT * DD) + (size_t)g * (TT * DD) + (size_t)t * DD;
        } else off = (size_t)row * DD;
        float4 v = *reinterpret_cast<const float4*>(xp + off + c4 * 4);
        float* dst = As + r * APAD + c4 * 4;
        dst[0] = v.x; dst[1] = v.y; dst[2] = v.z; dst[3] = v.w;
    }
    // load W tile, split hi/lo
    #pragma unroll
    for (int it = 0; it < 16; it++) {
        int f = tid + it * 256;
        int j = f >> 5, c4 = f & 31;
        float4 v = *reinterpret_cast<const float4*>(W + (size_t)(nbase + j) * DD + c4 * 4);
        float vv[4] = {v.x, v.y, v.z, v.w};
        #pragma unroll
        for (int q = 0; q < 4; q++) {
            uint32_t h = f2tf32(vv[q]);
            float lo = vv[q] - __uint_as_float(h);
            Bhi[j * APAD + c4 * 4 + q] = __uint_as_float(h);
            Blo[j * APAD + c4 * 4 + q] = __uint_as_float(f2tf32(lo));
        }
    }
    __syncthreads();

    const int wid = tid >> 5, lane = tid & 31;
    const int wm = wid & 1, wn = wid >> 1;       // warp tile: 64 rows x 32 cols
    const int grp = lane >> 2, tig = lane & 3;

    float acc[4][4][4];
    #pragma unroll
    for (int mt = 0; mt < 4; mt++)
        #pragma unroll
        for (int nt = 0; nt < 4; nt++)
            #pragma unroll
            for (int q = 0; q < 4; q++) acc[mt][nt][q] = 0.f;

    #pragma unroll
    for (int ks = 0; ks < 16; ks++) {
        const int k0 = ks * 8;
        uint32_t Ah[4][4], Al[4][4];
        #pragma unroll
        for (int mt = 0; mt < 4; mt++) {
            int r0 = wm * 64 + mt * 16 + grp;
            #pragma unroll
            for (int q = 0; q < 4; q++) {
                int rr = r0 + ((q & 1) ? 8 : 0);
                int cc = k0 + tig + ((q >= 2) ? 4 : 0);
                float a = As[rr * APAD + cc];
                uint32_t h = f2tf32(a);
                Ah[mt][q] = h;
                Al[mt][q] = f2tf32(a - __uint_as_float(h));
            }
        }
        uint32_t Bh[4][2], Bl[4][2];
        #pragma unroll
        for (int nt = 0; nt < 4; nt++) {
            int n0 = wn * 32 + nt * 8 + grp;
            #pragma unroll
            for (int q = 0; q < 2; q++) {
                int kk = k0 + tig + (q ? 4 : 0);
                Bh[nt][q] = __float_as_uint(Bhi[n0 * APAD + kk]);
                Bl[nt][q] = __float_as_uint(Blo[n0 * APAD + kk]);
            }
        }
        #pragma unroll
        for (int mt = 0; mt < 4; mt++)
            #pragma unroll
            for (int nt = 0; nt < 4; nt++) {
                mma_tf32(acc[mt][nt][0], acc[mt][nt][1], acc[mt][nt][2], acc[mt][nt][3],
                         Ah[mt][0], Ah[mt][1], Ah[mt][2], Ah[mt][3], Bh[nt][0], Bh[nt][1]);
                mma_tf32(acc[mt][nt][0], acc[mt][nt][1], acc[mt][nt][2], acc[mt][nt][3],
                         Ah[mt][0], Ah[mt][1], Ah[mt][2], Ah[mt][3], Bl[nt][0], Bl[nt][1]);
                mma_tf32(acc[mt][nt][0], acc[mt][nt][1], acc[mt][nt][2], acc[mt][nt][3],
                         Al[mt][0], Al[mt][1], Al[mt][2], Al[mt][3], Bh[nt][0], Bh[nt][1]);
            }
    }

    float* outp = g_GI + (size_t)g * GI_PER_G;
    #pragma unroll
    for (int nt = 0; nt < 4; nt++) {
        int cg = nbase + wn * 32 + nt * 8 + tig * 2;
        float b0 = bi[cg], b1 = bi[cg + 1];
        #pragma unroll
        for (int mt = 0; mt < 4; mt++) {
            int r0 = mbase + wm * 64 + mt * 16 + grp;
            float2 v0 = make_float2(acc[mt][nt][0] + b0, acc[mt][nt][1] + b1);
            float2 v1 = make_float2(acc[mt][nt][2] + b0, acc[mt][nt][3] + b1);
            *reinterpret_cast<float2*>(outp + (size_t)r0 * H3 + cg) = v0;
            *reinterpret_cast<float2*>(outp + (size_t)(r0 + 8) * H3 + cg) = v1;
        }
    }
}

// Phase 2: recurrence. grid (13,21), 256 thr, smem = 384*128*4 + 40*128*4
__global__ __launch_bounds__(256) void gru_rec_kernel(
    const float* __restrict__ Whh_lp, const float* __restrict__ bhh_lp,
    const float* __restrict__ Whh_ns, const float* __restrict__ bhh_ns)
{
    extern __shared__ float sm[];
    float* ws = sm;
    float* hs = sm + H3 * DD;
    const int g = blockIdx.y;
    const int base = blockIdx.x * 40;
    const int cnt = min(40, NNODES - base);
    const int tid = threadIdx.x;

    const float* W  = (g < LPN) ? (Whh_lp + (size_t)g * H3 * DD) : Whh_ns;
    const float* bh = (g < LPN) ? (bhh_lp + g * H3) : bhh_ns;

    const float4* W4 = reinterpret_cast<const float4*>(W);
    float4* ws4 = reinterpret_cast<float4*>(ws);
    for (int f = tid; f < H3 * DD / 4; f += 256) ws4[f] = W4[f];
    for (int f = tid; f < 40 * DD; f += 256) hs[f] = 0.f;

    const int ng = tid >> 5, dg = tid & 31;
    float bias[3][4];
    #pragma unroll
    for (int gg = 0; gg < 3; gg++)
        #pragma unroll
        for (int b = 0; b < 4; b++) bias[gg][b] = bh[gg * 128 + dg * 4 + b];
    __syncthreads();

    const float4* gi4 = reinterpret_cast<const float4*>(g_GI + (size_t)g * GI_PER_G);

    for (int t = 0; t < TT; t++) {
        float acc[3][4][5];
        #pragma unroll
        for (int gg = 0; gg < 3; gg++)
            #pragma unroll
            for (int b = 0; b < 4; b++)
                #pragma unroll
                for (int a = 0; a < 5; a++) acc[gg][b][a] = 0.f;

        #pragma unroll 2
        for (int k = 0; k < 128; k++) {
            int kk = k + dg; if (kk >= 128) kk -= 128;
            float hv[5];
            #pragma unroll
            for (int a = 0; a < 5; a++) hv[a] = hs[(ng + 8 * a) * 128 + kk];
            #pragma unroll
            for (int gg = 0; gg < 3; gg++)
                #pragma unroll
                for (int b = 0; b < 4; b++) {
                    float w = ws[(gg * 128 + dg * 4 + b) * 128 + kk];
                    #pragma unroll
                    for (int a = 0; a < 5; a++) acc[gg][b][a] += w * hv[a];
                }
        }
        __syncthreads();

        #pragma unroll
        for (int a = 0; a < 5; a++) {
            int nl = ng + 8 * a;
            if (nl < cnt) {
                int n = base + nl;
                size_t rb4 = ((size_t)n * TT + t) * (H3 / 4);
                float4 gr = gi4[rb4 + dg];
                float4 gz = gi4[rb4 + 32 + dg];
                float4 gn = gi4[rb4 + 64 + dg];
                float ir[4]  = {gr.x, gr.y, gr.z, gr.w};
                float iz[4]  = {gz.x, gz.y, gz.z, gz.w};
                float inn[4] = {gn.x, gn.y, gn.z, gn.w};
                float* hrow = hs + nl * 128 + dg * 4;
                #pragma unroll
                for (int b = 0; b < 4; b++) {
                    float r = sigm(ir[b] + acc[0][b][a] + bias[0][b]);
                    float z = sigm(iz[b] + acc[1][b][a] + bias[1][b]);
                    float nn = tanhf(inn[b] + r * (acc[2][b][a] + bias[2][b]));
                    hrow[b] = (1.f - z) * nn + z * hrow[b];
                }
            }
        }
        __syncthreads();
    }
    float* Hout = g_H + (size_t)g * NNODES * DD + (size_t)base * DD;
    for (int f = tid; f < cnt * DD; f += 256) Hout[f] = hs[f];
}

// C[m][n] = sum_k A[m][k]*B[n][k] (+bias). grid (M/32, ceil(N/32)), 256 thr
__global__ void gemm_tn_kernel(const float* __restrict__ A, int lda,
                               const float* __restrict__ B, int ldb,
                               const float* __restrict__ bias,
                               float* __restrict__ C, int ldc,
                               int M, int N, int K)
{
    __shared__ float As[32 * 32];
    __shared__ float Bs[32 * 33];
    const int rbase = blockIdx.x * 32;
    const int cbase = blockIdx.y * 32;
    const int tid = threadIdx.x;
    const int ty = tid >> 5, tx = tid & 31;

    float acc[4] = {0.f, 0.f, 0.f, 0.f};
    for (int kb = 0; kb < K; kb += 32) {
        #pragma unroll
        for (int i = 0; i < 4; i++) {
            int idx = tid + i * 256;
            int r = idx >> 5, kk = idx & 31;
            As[r * 32 + kk] = A[(size_t)(rbase + r) * lda + kb + kk];
            Bs[r * 33 + kk] = (cbase + r < N) ? B[(size_t)(cbase + r) * ldb + kb + kk] : 0.f;
        }
        __syncthreads();
        #pragma unroll
        for (int kk = 0; kk < 32; kk++) {
            float bv = Bs[tx * 33 + kk];
            #pragma unroll
            for (int i = 0; i < 4; i++)
                acc[i] += As[(ty + 8 * i) * 32 + kk] * bv;
        }
        __syncthreads();
    }
    if (cbase + tx < N) {
        float bb = bias ? bias[cbase + tx] : 0.f;
        #pragma unroll
        for (int i = 0; i < 4; i++)
            C[(size_t)(rbase + ty + 8 * i) * ldc + cbase + tx] = acc[i] + bb;
    }
}

__global__ void build_cat_kernel(const float* __restrict__ x_pdt,
                                 const float* __restrict__ x_ref,
                                 const float* __restrict__ x_def)
{
    int i = blockIdx.x * 256 + threadIdx.x;
    g_cat[i] = x_pdt[i];
    g_cat[NNODES * DD + i] = x_ref[i];
    g_cat[2 * NNODES * DD + i] = x_def[i];
    g_cat[4 * NNODES * DD + i] = g_H[(size_t)LPN * NNODES * DD + i];
}

__global__ void deg_init_kernel() {
    int i = blockIdx.x * 256 + threadIdx.x;
    if (i < NNODES) g_deg[i] = 1;
}
__global__ void deg_edge_kernel(const int* __restrict__ ei) {
    int e = blockIdx.x * 256 + threadIdx.x;
    if (e < NEDGES) atomicAdd(&g_deg[ei[NEDGES + e]], 1);
}
__global__ void dinv_kernel() {
    int i = blockIdx.x * 256 + threadIdx.x;
    if (i < NNODES) g_dinv[i] = rsqrtf((float)g_deg[i]);
}
__global__ void agg_init_kernel(const float* __restrict__ xw,
                                const float* __restrict__ bias,
                                float* __restrict__ out)
{
    int i = blockIdx.x * 256 + threadIdx.x;
    int n = i >> 7, d = i & 127;
    float di = g_dinv[n];
    out[i] = bias[d] + di * di * xw[i];
}
__global__ void agg_edge_kernel(const float* __restrict__ xw,
                                const int* __restrict__ ei,
                                float* __restrict__ out)
{
    int i = blockIdx.x * 256 + threadIdx.x;
    int e = i >> 7, d = i & 127;
    int s = ei[e], t = ei[NEDGES + e];
    atomicAdd(&out[t * 128 + d], xw[s * 128 + d] * g_dinv[s] * g_dinv[t]);
}
__global__ void relu_ln_kernel(const float* __restrict__ in,
                               const float* __restrict__ gam,
                               const float* __restrict__ bet,
                               float* __restrict__ out)
{
    int row = blockIdx.x, d = threadIdx.x;
    float v = fmaxf(in[row * 128 + d], 0.f);
    float s = v, sq = v * v;
    #pragma unroll
    for (int o = 16; o > 0; o >>= 1) {
        s  += __shfl_xor_sync(0xffffffffu, s, o);
        sq += __shfl_xor_sync(0xffffffffu, sq, o);
    }
    __shared__ float ss[4], ssq[4];
    int w = d >> 5, l = d & 31;
    if (l == 0) { ss[w] = s; ssq[w] = sq; }
    __syncthreads();
    float st = ss[0] + ss[1] + ss[2] + ss[3];
    float sqt = ssq[0] + ssq[1] + ssq[2] + ssq[3];
    float m = st * (1.f / 128.f);
    float var = sqt * (1.f / 128.f) - m * m;
    out[row * 128 + d] = (v - m) * rsqrtf(var + LN_EPS) * gam[d] + bet[d];
}
__global__ void relu_kernel(const float* __restrict__ in, float* __restrict__ out) {
    int i = blockIdx.x * 256 + threadIdx.x;
    if (i < NNODES * DD) out[i] = fmaxf(in[i], 0.f);
}
__global__ void logsoftmax_kernel(float* __restrict__ out) {
    int i = blockIdx.x * 256 + threadIdx.x;
    if (i < NNODES) {
        float a = g_logits[2 * i], b = g_logits[2 * i + 1];
        float m = fmaxf(a, b);
        float lse = m + logf(expf(a - m) + expf(b - m));
        out[2 * i] = a - lse;
        out[2 * i + 1] = b - lse;
    }
}

extern "C" void kernel_launch(void* const* d_in, const int* in_sizes, int n_in,
                              void* d_out, int out_size)
{
    const float* x_lp    = (const float*)d_in[0];
    const float* x_ns    = (const float*)d_in[1];
    const float* x_ref   = (const float*)d_in[2];
    const float* x_def   = (const float*)d_in[3];
    const float* x_pdt   = (const float*)d_in[4];
    const int*   edge    = (const int*)  d_in[5];
    const float* Wih_lp  = (const float*)d_in[6];
    const float* Whh_lp  = (const float*)d_in[7];
    const float* bih_lp  = (const float*)d_in[8];
    const float* bhh_lp  = (const float*)d_in[9];
    const float* lp_fc_W = (const float*)d_in[10];
    const float* lp_fc_b = (const float*)d_in[11];
    const float* Wih_ns  = (const float*)d_in[12];
    const float* Whh_ns  = (const float*)d_in[13];
    const float* bih_ns  = (const float*)d_in[14];
    const float* bhh_ns  = (const float*)d_in[15];
    const float* all_fc_W = (const float*)d_in[16];
    const float* all_fc_b = (const float*)d_in[17];
    const float* convW[3] = {(const float*)d_in[18], (const float*)d_in[20], (const float*)d_in[22]};
    const float* convB[3] = {(const float*)d_in[19], (const float*)d_in[21], (const float*)d_in[23]};
    const float* lnG[2] = {(const float*)d_in[24], (const float*)d_in[26]};
    const float* lnB[2] = {(const float*)d_in[25], (const float*)d_in[27]};
    const float* mp1_W = (const float*)d_in[28];
    const float* mp1_b = (const float*)d_in[29];
    const float* mp2_W = (const float*)d_in[30];
    const float* mp2_b = (const float*)d_in[31];
    float* out = (float*)d_out;
    (void)in_sizes; (void)n_in; (void)out_size;

    float *H, *cat, *bufA, *bufB, *bufC, *logits;
    cudaGetSymbolAddress((void**)&H, g_H);
    cudaGetSymbolAddress((void**)&cat, g_cat);
    cudaGetSymbolAddress((void**)&bufA, g_bufA);
    cudaGetSymbolAddress((void**)&bufB, g_bufB);
    cudaGetSymbolAddress((void**)&bufC, g_bufC);
    cudaGetSymbolAddress((void**)&logits, g_logits);

    const int gi_smem = 3 * 128 * APAD * 4;
    cudaFuncSetAttribute(gi_mma_kernel, cudaFuncAttributeMaxDynamicSharedMemorySize, gi_smem);
    cudaFuncSetAttribute(gru_rec_kernel, cudaFuncAttributeMaxDynamicSharedMemorySize, 217088);

    gi_mma_kernel<<<dim3(240, 3, NGRU), 256, gi_smem>>>(x_lp, x_ns, Wih_lp, bih_lp, Wih_ns, bih_ns);
    gru_rec_kernel<<<dim3(13, NGRU), 256, 217088>>>(Whh_lp, bhh_lp, Whh_ns, bhh_ns);

    // lp_fc: [512, 2560] @ lp_fc_W^T -> cat segment 3
    gemm_tn_kernel<<<dim3(16, 4), 256>>>(H, LPN * DD, lp_fc_W, LPN * DD, lp_fc_b,
                                         cat + 3 * NNODES * DD, DD, NNODES, DD, LPN * DD);
    build_cat_kernel<<<256, 256>>>(x_pdt, x_ref, x_def);
    // all_fc: [512, 640] -> bufA
    gemm_tn_kernel<<<dim3(16, 4), 256>>>(cat, 5 * DD, all_fc_W, 5 * DD, all_fc_b,
                                         bufA, DD, NNODES, DD, 5 * DD);

    deg_init_kernel<<<2, 256>>>();
    deg_edge_kernel<<<NEDGES / 256, 256>>>(edge);
    dinv_kernel<<<2, 256>>>();

    // conv0
    gemm_tn_kernel<<<dim3(16, 4), 256>>>(bufA, DD, convW[0], DD, nullptr, bufB, DD, NNODES, DD, DD);
    agg_init_kernel<<<256, 256>>>(bufB, convB[0], bufC);
    agg_edge_kernel<<<NEDGES * DD / 256, 256>>>(bufB, edge, bufC);
    relu_ln_kernel<<<NNODES, 128>>>(bufC, lnG[0], lnB[0], bufA);
    // conv1
    gemm_tn_kernel<<<dim3(16, 4), 256>>>(bufA, DD, convW[1], DD, nullptr, bufB, DD, NNODES, DD, DD);
    agg_init_kernel<<<256, 256>>>(bufB, convB[1], bufC);
    agg_edge_kernel<<<NEDGES * DD / 256, 256>>>(bufB, edge, bufC);
    relu_ln_kernel<<<NNODES, 128>>>(bufC, lnG[1], lnB[1], bufA);
    // conv2 -> emb straight to d_out[0:65536]
    gemm_tn_kernel<<<dim3(16, 4), 256>>>(bufA, DD, convW[2], DD, nullptr, bufB, DD, NNODES, DD, DD);
    agg_init_kernel<<<256, 256>>>(bufB, convB[2], out);
    agg_edge_kernel<<<NEDGES * DD / 256, 256>>>(bufB, edge, out);
    relu_kernel<<<256, 256>>>(out, bufA);
    // mp1, mp2
    gemm_tn_kernel<<<dim3(16, 4), 256>>>(bufA, DD, mp1_W, DD, mp1_b, bufB, DD, NNODES, DD, DD);
    gemm_tn_kernel<<<dim3(16, 1), 256>>>(bufB, DD, mp2_W, DD, mp2_b, logits, 2, NNODES, 2, DD);
    logsoftmax_kernel<<<2, 256>>>(out + NNODES * DD);
}

// round 5
// speedup vs baseline: 1.6734x; 1.4491x over previous
#include <cuda_runtime.h>
#include <cuda_bf16.h>
#include <math.h>
#include <stdint.h>

#define NNODES 512
#define NEDGES 16384
#define LPN 20
#define TT 60
#define DD 128
#define H3 384
#define NGRU 21
#define GI_PER_G (NNODES*TT*H3)
#define LN_EPS 1e-5f

__device__ float g_GI[(size_t)NGRU * GI_PER_G];
__device__ float g_H[NGRU * NNODES * DD];
__device__ float g_cat[5 * NNODES * DD];
__device__ float g_bufA[NNODES * DD];
__device__ float g_bufB[NNODES * DD];
__device__ float g_bufC[NNODES * DD];
__device__ int   g_deg[NNODES];
__device__ float g_dinv[NNODES];
__device__ float g_logits[NNODES * 2];

__device__ __forceinline__ float sigm(float x) { return 1.f / (1.f + expf(-x)); }
__device__ __forceinline__ float sigmf_(float x) { return 1.f / (1.f + __expf(-x)); }
__device__ __forceinline__ float tanhf_(float x) {
    x = fminf(fmaxf(x, -15.f), 15.f);
    float e = __expf(2.f * x);
    return (e - 1.f) / (e + 1.f);
}

__device__ __forceinline__ uint32_t f2tf32(float a) {
    uint32_t r;
    asm("cvt.rna.tf32.f32 %0, %1;" : "=r"(r) : "f"(a));
    return r;
}
__device__ __forceinline__ void mma_tf32(float& d0, float& d1, float& d2, float& d3,
                                         uint32_t a0, uint32_t a1, uint32_t a2, uint32_t a3,
                                         uint32_t b0, uint32_t b1) {
    asm volatile("mma.sync.aligned.m16n8k8.row.col.f32.tf32.tf32.f32 "
                 "{%0,%1,%2,%3}, {%4,%5,%6,%7}, {%8,%9}, {%0,%1,%2,%3};"
                 : "+f"(d0), "+f"(d1), "+f"(d2), "+f"(d3)
                 : "r"(a0), "r"(a1), "r"(a2), "r"(a3), "r"(b0), "r"(b1));
}
__device__ __forceinline__ void mma_bf16(float* d, const uint32_t* a, uint32_t b0, uint32_t b1) {
    asm volatile("mma.sync.aligned.m16n8k16.row.col.f32.bf16.bf16.f32 "
                 "{%0,%1,%2,%3}, {%4,%5,%6,%7}, {%8,%9}, {%0,%1,%2,%3};"
                 : "+f"(d[0]), "+f"(d[1]), "+f"(d[2]), "+f"(d[3])
                 : "r"(a[0]), "r"(a[1]), "r"(a[2]), "r"(a[3]), "r"(b0), "r"(b1));
}
// split two fp32 into packed bf16x2 hi and lo words (x = low half)
__device__ __forceinline__ void split2(float x, float y, uint32_t& hi, uint32_t& lo) {
    __nv_bfloat16 hx = __float2bfloat16(x);
    __nv_bfloat16 hy = __float2bfloat16(y);
    float rx = x - __bfloat162float(hx);
    float ry = y - __bfloat162float(hy);
    __nv_bfloat16 lx = __float2bfloat16(rx);
    __nv_bfloat16 ly = __float2bfloat16(ry);
    hi = ((uint32_t)__bfloat16_as_ushort(hy) << 16) | (uint32_t)__bfloat16_as_ushort(hx);
    lo = ((uint32_t)__bfloat16_as_ushort(ly) << 16) | (uint32_t)__bfloat16_as_ushort(lx);
}

// ---------------- Phase 1 (tf32x3 MMA): gi = x @ Wih^T + bih ---------------
#define APAD 132
__global__ __launch_bounds__(256) void gi_mma_kernel(
    const float* __restrict__ x_lp, const float* __restrict__ x_ns,
    const float* __restrict__ Wih_lp, const float* __restrict__ bih_lp,
    const float* __restrict__ Wih_ns, const float* __restrict__ bih_ns)
{
    extern __shared__ float sm[];
    float* As  = sm;
    float* Bhi = sm + 128 * APAD;
    float* Blo = sm + 2 * 128 * APAD;
    const int g = blockIdx.z;
    const int mbase = blockIdx.x * 128;
    const int nbase = blockIdx.y * 128;
    const int tid = threadIdx.x;

    const float* W  = (g < LPN) ? (Wih_lp + (size_t)g * H3 * DD) : Wih_ns;
    const float* bi = (g < LPN) ? (bih_lp + g * H3) : bih_ns;
    const float* xp = (g < LPN) ? x_lp : x_ns;

    #pragma unroll
    for (int it = 0; it < 16; it++) {
        int f = tid + it * 256;
        int r = f >> 5, c4 = f & 31;
        int row = mbase + r;
        size_t off;
        if (g < LPN) {
            int n = row / TT, t = row - n * TT;
            off = (size_t)n * (LPN * TT * DD) + (size_t)g * (TT * DD) + (size_t)t * DD;
        } else off = (size_t)row * DD;
        float4 v = *reinterpret_cast<const float4*>(xp + off + c4 * 4);
        float* dst = As + r * APAD + c4 * 4;
        dst[0] = v.x; dst[1] = v.y; dst[2] = v.z; dst[3] = v.w;
    }
    #pragma unroll
    for (int it = 0; it < 16; it++) {
        int f = tid + it * 256;
        int j = f >> 5, c4 = f & 31;
        float4 v = *reinterpret_cast<const float4*>(W + (size_t)(nbase + j) * DD + c4 * 4);
        float vv[4] = {v.x, v.y, v.z, v.w};
        #pragma unroll
        for (int q = 0; q < 4; q++) {
            uint32_t h = f2tf32(vv[q]);
            float lo = vv[q] - __uint_as_float(h);
            Bhi[j * APAD + c4 * 4 + q] = __uint_as_float(h);
            Blo[j * APAD + c4 * 4 + q] = __uint_as_float(f2tf32(lo));
        }
    }
    __syncthreads();

    const int wid = tid >> 5, lane = tid & 31;
    const int wm = wid & 1, wn = wid >> 1;
    const int grp = lane >> 2, tig = lane & 3;

    float acc[4][4][4];
    #pragma unroll
    for (int mt = 0; mt < 4; mt++)
        #pragma unroll
        for (int nt = 0; nt < 4; nt++)
            #pragma unroll
            for (int q = 0; q < 4; q++) acc[mt][nt][q] = 0.f;

    #pragma unroll
    for (int ks = 0; ks < 16; ks++) {
        const int k0 = ks * 8;
        uint32_t Ah[4][4], Al[4][4];
        #pragma unroll
        for (int mt = 0; mt < 4; mt++) {
            int r0 = wm * 64 + mt * 16 + grp;
            #pragma unroll
            for (int q = 0; q < 4; q++) {
                int rr = r0 + ((q & 1) ? 8 : 0);
                int cc = k0 + tig + ((q >= 2) ? 4 : 0);
                float a = As[rr * APAD + cc];
                uint32_t h = f2tf32(a);
                Ah[mt][q] = h;
                Al[mt][q] = f2tf32(a - __uint_as_float(h));
            }
        }
        uint32_t Bh[4][2], Bl[4][2];
        #pragma unroll
        for (int nt = 0; nt < 4; nt++) {
            int n0 = wn * 32 + nt * 8 + grp;
            #pragma unroll
            for (int q = 0; q < 2; q++) {
                int kk = k0 + tig + (q ? 4 : 0);
                Bh[nt][q] = __float_as_uint(Bhi[n0 * APAD + kk]);
                Bl[nt][q] = __float_as_uint(Blo[n0 * APAD + kk]);
            }
        }
        #pragma unroll
        for (int mt = 0; mt < 4; mt++)
            #pragma unroll
            for (int nt = 0; nt < 4; nt++) {
                mma_tf32(acc[mt][nt][0], acc[mt][nt][1], acc[mt][nt][2], acc[mt][nt][3],
                         Ah[mt][0], Ah[mt][1], Ah[mt][2], Ah[mt][3], Bh[nt][0], Bh[nt][1]);
                mma_tf32(acc[mt][nt][0], acc[mt][nt][1], acc[mt][nt][2], acc[mt][nt][3],
                         Ah[mt][0], Ah[mt][1], Ah[mt][2], Ah[mt][3], Bl[nt][0], Bl[nt][1]);
                mma_tf32(acc[mt][nt][0], acc[mt][nt][1], acc[mt][nt][2], acc[mt][nt][3],
                         Al[mt][0], Al[mt][1], Al[mt][2], Al[mt][3], Bh[nt][0], Bh[nt][1]);
            }
    }

    float* outp = g_GI + (size_t)g * GI_PER_G;
    #pragma unroll
    for (int nt = 0; nt < 4; nt++) {
        int cg = nbase + wn * 32 + nt * 8 + tig * 2;
        float b0 = bi[cg], b1 = bi[cg + 1];
        #pragma unroll
        for (int mt = 0; mt < 4; mt++) {
            int r0 = mbase + wm * 64 + mt * 16 + grp;
            *reinterpret_cast<float2*>(outp + (size_t)r0 * H3 + cg) =
                make_float2(acc[mt][nt][0] + b0, acc[mt][nt][1] + b1);
            *reinterpret_cast<float2*>(outp + (size_t)(r0 + 8) * H3 + cg) =
                make_float2(acc[mt][nt][2] + b0, acc[mt][nt][3] + b1);
        }
    }
}

// ---------------- Phase 2 (bf16x3 MMA recurrence) --------------------------
// grid (16, 21): 32 nodes per CTA. 8 warps, warp w owns hidden cols [w*16, w*16+16).
// smem (uint32 words): WHI[384][68], WLO[384][68], HHI[32][68], HLO[32][68]
#define WSTR 68
#define SM_WHI 0
#define SM_WLO (384*WSTR)
#define SM_HHI (2*384*WSTR)
#define SM_HLO (2*384*WSTR + 32*WSTR)
#define GRU_SMEM ((2*384*WSTR + 2*32*WSTR) * 4)

__global__ __launch_bounds__(256) void gru_mma_kernel(
    const float* __restrict__ Whh_lp, const float* __restrict__ bhh_lp,
    const float* __restrict__ Whh_ns, const float* __restrict__ bhh_ns)
{
    extern __shared__ uint32_t su[];
    uint32_t* WHI = su + SM_WHI;
    uint32_t* WLO = su + SM_WLO;
    uint32_t* HHI = su + SM_HHI;
    uint32_t* HLO = su + SM_HLO;
    const int g = blockIdx.y;
    const int base = blockIdx.x * 32;
    const int tid = threadIdx.x;

    const float* Wp = (g < LPN) ? (Whh_lp + (size_t)g * H3 * DD) : Whh_ns;
    const float* bh = (g < LPN) ? (bhh_lp + g * H3) : bhh_ns;

    // split Whh into bf16 hi/lo packed words
    for (int idx = tid; idx < 384 * 64; idx += 256) {
        int n = idx >> 6, j = idx & 63;
        float2 wv = *reinterpret_cast<const float2*>(Wp + (size_t)n * DD + 2 * j);
        uint32_t hi, lo;
        split2(wv.x, wv.y, hi, lo);
        WHI[n * WSTR + j] = hi;
        WLO[n * WSTR + j] = lo;
    }
    for (int idx = tid; idx < 32 * WSTR; idx += 256) { HHI[idx] = 0u; HLO[idx] = 0u; }

    const int w = tid >> 5, lane = tid & 31;
    const int grp = lane >> 2, tig = lane & 3;

    // bias regs: [gate][cc], col(cc) = w*16 + (cc>>1)*8 + 2*tig + (cc&1)
    float bias[3][4];
    #pragma unroll
    for (int gate = 0; gate < 3; gate++)
        #pragma unroll
        for (int cc = 0; cc < 4; cc++)
            bias[gate][cc] = bh[gate * 128 + w * 16 + (cc >> 1) * 8 + 2 * tig + (cc & 1)];

    // n-rows for this warp's 6 B tiles: nt -> gate=nt>>1, half=nt&1
    int nrow[6];
    #pragma unroll
    for (int nt = 0; nt < 6; nt++)
        nrow[nt] = (nt >> 1) * 128 + w * 16 + (nt & 1) * 8 + grp;

    float hreg[4][4];
    #pragma unroll
    for (int mi = 0; mi < 4; mi++)
        #pragma unroll
        for (int cc = 0; cc < 4; cc++) hreg[mi][cc] = 0.f;

    __syncthreads();

    const float* gib = g_GI + (size_t)g * GI_PER_G;

    for (int t = 0; t < TT; t++) {
        // prefetch gi for this lane's 4 rows x 3 gates x 2 col-halves
        float2 gi2[4][3][2];
        #pragma unroll
        for (int mi = 0; mi < 4; mi++) {
            int node = base + (mi >> 1) * 16 + (mi & 1) * 8 + grp;
            const float* rowp = gib + ((size_t)node * TT + t) * H3 + w * 16 + 2 * tig;
            #pragma unroll
            for (int gate = 0; gate < 3; gate++) {
                gi2[mi][gate][0] = *reinterpret_cast<const float2*>(rowp + gate * 128);
                gi2[mi][gate][1] = *reinterpret_cast<const float2*>(rowp + gate * 128 + 8);
            }
        }

        float acc[2][6][4];
        #pragma unroll
        for (int mt = 0; mt < 2; mt++)
            #pragma unroll
            for (int nt = 0; nt < 6; nt++)
                #pragma unroll
                for (int q = 0; q < 4; q++) acc[mt][nt][q] = 0.f;

        #pragma unroll
        for (int kt = 0; kt < 8; kt++) {
            uint32_t ahi[2][4], alo[2][4];
            #pragma unroll
            for (int mt = 0; mt < 2; mt++) {
                int r0 = mt * 16 + grp;
                ahi[mt][0] = HHI[r0 * WSTR + kt * 8 + tig];
                ahi[mt][1] = HHI[(r0 + 8) * WSTR + kt * 8 + tig];
                ahi[mt][2] = HHI[r0 * WSTR + kt * 8 + 4 + tig];
                ahi[mt][3] = HHI[(r0 + 8) * WSTR + kt * 8 + 4 + tig];
                alo[mt][0] = HLO[r0 * WSTR + kt * 8 + tig];
                alo[mt][1] = HLO[(r0 + 8) * WSTR + kt * 8 + tig];
                alo[mt][2] = HLO[r0 * WSTR + kt * 8 + 4 + tig];
                alo[mt][3] = HLO[(r0 + 8) * WSTR + kt * 8 + 4 + tig];
            }
            #pragma unroll
            for (int nt = 0; nt < 6; nt++) {
                uint32_t bh0 = WHI[nrow[nt] * WSTR + kt * 8 + tig];
                uint32_t bh1 = WHI[nrow[nt] * WSTR + kt * 8 + 4 + tig];
                uint32_t bl0 = WLO[nrow[nt] * WSTR + kt * 8 + tig];
                uint32_t bl1 = WLO[nrow[nt] * WSTR + kt * 8 + 4 + tig];
                #pragma unroll
                for (int mt = 0; mt < 2; mt++) {
                    mma_bf16(acc[mt][nt], ahi[mt], bh0, bh1);
                    mma_bf16(acc[mt][nt], ahi[mt], bl0, bl1);
                    mma_bf16(acc[mt][nt], alo[mt], bh0, bh1);
                }
            }
        }
        __syncthreads();   // all MMA reads of H done before overwrite

        // epilogue: gates + h update (h carried exactly in fp32 regs)
        #pragma unroll
        for (int mt = 0; mt < 2; mt++)
            #pragma unroll
            for (int rh = 0; rh < 2; rh++) {
                int mi = mt * 2 + rh;
                #pragma unroll
                for (int hf = 0; hf < 2; hf++)
                    #pragma unroll
                    for (int cl = 0; cl < 2; cl++) {
                        int q = rh * 2 + cl;
                        int cc = hf * 2 + cl;
                        float gr = cl ? gi2[mi][0][hf].y : gi2[mi][0][hf].x;
                        float gz = cl ? gi2[mi][1][hf].y : gi2[mi][1][hf].x;
                        float gn = cl ? gi2[mi][2][hf].y : gi2[mi][2][hf].x;
                        float r = sigmf_(gr + acc[mt][0 + hf][q] + bias[0][cc]);
                        float z = sigmf_(gz + acc[mt][2 + hf][q] + bias[1][cc]);
                        float nn = tanhf_(gn + r * (acc[mt][4 + hf][q] + bias[2][cc]));
                        hreg[mi][cc] = (1.f - z) * nn + z * hreg[mi][cc];
                    }
            }
        // store h (split bf16 hi/lo) for next step's A operand
        #pragma unroll
        for (int mi = 0; mi < 4; mi++) {
            int row = (mi >> 1) * 16 + (mi & 1) * 8 + grp;
            uint32_t hi0, lo0, hi1, lo1;
            split2(hreg[mi][0], hreg[mi][1], hi0, lo0);
            split2(hreg[mi][2], hreg[mi][3], hi1, lo1);
            HHI[row * WSTR + w * 8 + tig] = hi0;
            HLO[row * WSTR + w * 8 + tig] = lo0;
            HHI[row * WSTR + w * 8 + 4 + tig] = hi1;
            HLO[row * WSTR + w * 8 + 4 + tig] = lo1;
        }
        __syncthreads();
    }

    // writeout final h
    #pragma unroll
    for (int mi = 0; mi < 4; mi++) {
        int node = base + (mi >> 1) * 16 + (mi & 1) * 8 + grp;
        float* op = g_H + ((size_t)g * NNODES + node) * DD + w * 16;
        #pragma unroll
        for (int cc = 0; cc < 4; cc++)
            op[(cc >> 1) * 8 + 2 * tig + (cc & 1)] = hreg[mi][cc];
    }
}

// ---------------- tail kernels (unchanged) ----------------
__global__ void gemm_tn_kernel(const float* __restrict__ A, int lda,
                               const float* __restrict__ B, int ldb,
                               const float* __restrict__ bias,
                               float* __restrict__ C, int ldc,
                               int M, int N, int K)
{
    __shared__ float As[32 * 32];
    __shared__ float Bs[32 * 33];
    const int rbase = blockIdx.x * 32;
    const int cbase = blockIdx.y * 32;
    const int tid = threadIdx.x;
    const int ty = tid >> 5, tx = tid & 31;

    float acc[4] = {0.f, 0.f, 0.f, 0.f};
    for (int kb = 0; kb < K; kb += 32) {
        #pragma unroll
        for (int i = 0; i < 4; i++) {
            int idx = tid + i * 256;
            int r = idx >> 5, kk = idx & 31;
            As[r * 32 + kk] = A[(size_t)(rbase + r) * lda + kb + kk];
            Bs[r * 33 + kk] = (cbase + r < N) ? B[(size_t)(cbase + r) * ldb + kb + kk] : 0.f;
        }
        __syncthreads();
        #pragma unroll
        for (int kk = 0; kk < 32; kk++) {
            float bv = Bs[tx * 33 + kk];
            #pragma unroll
            for (int i = 0; i < 4; i++)
                acc[i] += As[(ty + 8 * i) * 32 + kk] * bv;
        }
        __syncthreads();
    }
    if (cbase + tx < N) {
        float bb = bias ? bias[cbase + tx] : 0.f;
        #pragma unroll
        for (int i = 0; i < 4; i++)
            C[(size_t)(rbase + ty + 8 * i) * ldc + cbase + tx] = acc[i] + bb;
    }
}

__global__ void build_cat_kernel(const float* __restrict__ x_pdt,
                                 const float* __restrict__ x_ref,
                                 const float* __restrict__ x_def)
{
    int i = blockIdx.x * 256 + threadIdx.x;
    g_cat[i] = x_pdt[i];
    g_cat[NNODES * DD + i] = x_ref[i];
    g_cat[2 * NNODES * DD + i] = x_def[i];
    g_cat[4 * NNODES * DD + i] = g_H[(size_t)LPN * NNODES * DD + i];
}

__global__ void deg_init_kernel() {
    int i = blockIdx.x * 256 + threadIdx.x;
    if (i < NNODES) g_deg[i] = 1;
}
__global__ void deg_edge_kernel(const int* __restrict__ ei) {
    int e = blockIdx.x * 256 + threadIdx.x;
    if (e < NEDGES) atomicAdd(&g_deg[ei[NEDGES + e]], 1);
}
__global__ void dinv_kernel() {
    int i = blockIdx.x * 256 + threadIdx.x;
    if (i < NNODES) g_dinv[i] = rsqrtf((float)g_deg[i]);
}
__global__ void agg_init_kernel(const float* __restrict__ xw,
                                const float* __restrict__ bias,
                                float* __restrict__ out)
{
    int i = blockIdx.x * 256 + threadIdx.x;
    int n = i >> 7, d = i & 127;
    float di = g_dinv[n];
    out[i] = bias[d] + di * di * xw[i];
}
__global__ void agg_edge_kernel(const float* __restrict__ xw,
                                const int* __restrict__ ei,
                                float* __restrict__ out)
{
    int i = blockIdx.x * 256 + threadIdx.x;
    int e = i >> 7, d = i & 127;
    int s = ei[e], t = ei[NEDGES + e];
    atomicAdd(&out[t * 128 + d], xw[s * 128 + d] * g_dinv[s] * g_dinv[t]);
}
__global__ void relu_ln_kernel(const float* __restrict__ in,
                               const float* __restrict__ gam,
                               const float* __restrict__ bet,
                               float* __restrict__ out)
{
    int row = blockIdx.x, d = threadIdx.x;
    float v = fmaxf(in[row * 128 + d], 0.f);
    float s = v, sq = v * v;
    #pragma unroll
    for (int o = 16; o > 0; o >>= 1) {
        s  += __shfl_xor_sync(0xffffffffu, s, o);
        sq += __shfl_xor_sync(0xffffffffu, sq, o);
    }
    __shared__ float ss[4], ssq[4];
    int w = d >> 5, l = d & 31;
    if (l == 0) { ss[w] = s; ssq[w] = sq; }
    __syncthreads();
    float st = ss[0] + ss[1] + ss[2] + ss[3];
    float sqt = ssq[0] + ssq[1] + ssq[2] + ssq[3];
    float m = st * (1.f / 128.f);
    float var = sqt * (1.f / 128.f) - m * m;
    out[row * 128 + d] = (v - m) * rsqrtf(var + LN_EPS) * gam[d] + bet[d];
}
__global__ void relu_kernel(const float* __restrict__ in, float* __restrict__ out) {
    int i = blockIdx.x * 256 + threadIdx.x;
    if (i < NNODES * DD) out[i] = fmaxf(in[i], 0.f);
}
__global__ void logsoftmax_kernel(float* __restrict__ out) {
    int i = blockIdx.x * 256 + threadIdx.x;
    if (i < NNODES) {
        float a = g_logits[2 * i], b = g_logits[2 * i + 1];
        float m = fmaxf(a, b);
        float lse = m + logf(expf(a - m) + expf(b - m));
        out[2 * i] = a - lse;
        out[2 * i + 1] = b - lse;
    }
}

extern "C" void kernel_launch(void* const* d_in, const int* in_sizes, int n_in,
                              void* d_out, int out_size)
{
    const float* x_lp    = (const float*)d_in[0];
    const float* x_ns    = (const float*)d_in[1];
    const float* x_ref   = (const float*)d_in[2];
    const float* x_def   = (const float*)d_in[3];
    const float* x_pdt   = (const float*)d_in[4];
    const int*   edge    = (const int*)  d_in[5];
    const float* Wih_lp  = (const float*)d_in[6];
    const float* Whh_lp  = (const float*)d_in[7];
    const float* bih_lp  = (const float*)d_in[8];
    const float* bhh_lp  = (const float*)d_in[9];
    const float* lp_fc_W = (const float*)d_in[10];
    const float* lp_fc_b = (const float*)d_in[11];
    const float* Wih_ns  = (const float*)d_in[12];
    const float* Whh_ns  = (const float*)d_in[13];
    const float* bih_ns  = (const float*)d_in[14];
    const float* bhh_ns  = (const float*)d_in[15];
    const float* all_fc_W = (const float*)d_in[16];
    const float* all_fc_b = (const float*)d_in[17];
    const float* convW[3] = {(const float*)d_in[18], (const float*)d_in[20], (const float*)d_in[22]};
    const float* convB[3] = {(const float*)d_in[19], (const float*)d_in[21], (const float*)d_in[23]};
    const float* lnG[2] = {(const float*)d_in[24], (const float*)d_in[26]};
    const float* lnB[2] = {(const float*)d_in[25], (const float*)d_in[27]};
    const float* mp1_W = (const float*)d_in[28];
    const float* mp1_b = (const float*)d_in[29];
    const float* mp2_W = (const float*)d_in[30];
    const float* mp2_b = (const float*)d_in[31];
    float* out = (float*)d_out;
    (void)in_sizes; (void)n_in; (void)out_size;

    float *H, *cat, *bufA, *bufB, *bufC, *logits;
    cudaGetSymbolAddress((void**)&H, g_H);
    cudaGetSymbolAddress((void**)&cat, g_cat);
    cudaGetSymbolAddress((void**)&bufA, g_bufA);
    cudaGetSymbolAddress((void**)&bufB, g_bufB);
    cudaGetSymbolAddress((void**)&bufC, g_bufC);
    cudaGetSymbolAddress((void**)&logits, g_logits);

    const int gi_smem = 3 * 128 * APAD * 4;
    cudaFuncSetAttribute(gi_mma_kernel, cudaFuncAttributeMaxDynamicSharedMemorySize, gi_smem);
    cudaFuncSetAttribute(gru_mma_kernel, cudaFuncAttributeMaxDynamicSharedMemorySize, GRU_SMEM);

    // order chosen so the ncu capture slot lands on gru_mma_kernel
    gi_mma_kernel<<<dim3(240, 3, NGRU), 256, gi_smem>>>(x_lp, x_ns, Wih_lp, bih_lp, Wih_ns, bih_ns);
    deg_init_kernel<<<2, 256>>>();
    deg_edge_kernel<<<NEDGES / 256, 256>>>(edge);
    gru_mma_kernel<<<dim3(16, NGRU), 256, GRU_SMEM>>>(Whh_lp, bhh_lp, Whh_ns, bhh_ns);
    dinv_kernel<<<2, 256>>>();

    gemm_tn_kernel<<<dim3(16, 4), 256>>>(H, LPN * DD, lp_fc_W, LPN * DD, lp_fc_b,
                                         cat + 3 * NNODES * DD, DD, NNODES, DD, LPN * DD);
    build_cat_kernel<<<256, 256>>>(x_pdt, x_ref, x_def);
    gemm_tn_kernel<<<dim3(16, 4), 256>>>(cat, 5 * DD, all_fc_W, 5 * DD, all_fc_b,
                                         bufA, DD, NNODES, DD, 5 * DD);

    // conv0
    gemm_tn_kernel<<<dim3(16, 4), 256>>>(bufA, DD, convW[0], DD, nullptr, bufB, DD, NNODES, DD, DD);
    agg_init_kernel<<<256, 256>>>(bufB, convB[0], bufC);
    agg_edge_kernel<<<NEDGES * DD / 256, 256>>>(bufB, edge, bufC);
    relu_ln_kernel<<<NNODES, 128>>>(bufC, lnG[0], lnB[0], bufA);
    // conv1
    gemm_tn_kernel<<<dim3(16, 4), 256>>>(bufA, DD, convW[1], DD, nullptr, bufB, DD, NNODES, DD, DD);
    agg_init_kernel<<<256, 256>>>(bufB, convB[1], bufC);
    agg_edge_kernel<<<NEDGES * DD / 256, 256>>>(bufB, edge, bufC);
    relu_ln_kernel<<<NNODES, 128>>>(bufC, lnG[1], lnB[1], bufA);
    // conv2 -> emb straight to d_out[0:65536]
    gemm_tn_kernel<<<dim3(16, 4), 256>>>(bufA, DD, convW[2], DD, nullptr, bufB, DD, NNODES, DD, DD);
    agg_init_kernel<<<256, 256>>>(bufB, convB[2], out);
    agg_edge_kernel<<<NEDGES * DD / 256, 256>>>(bufB, edge, out);
    relu_kernel<<<256, 256>>>(out, bufA);
    // mp1, mp2
    gemm_tn_kernel<<<dim3(16, 4), 256>>>(bufA, DD, mp1_W, DD, mp1_b, bufB, DD, NNODES, DD, DD);
    gemm_tn_kernel<<<dim3(16, 1), 256>>>(bufB, DD, mp2_W, DD, mp2_b, logits, 2, NNODES, 2, DD);
    logsoftmax_kernel<<<2, 256>>>(out + NNODES * DD);
}

// round 7
// speedup vs baseline: 1.6887x; 1.0091x over previous
#include <cuda_runtime.h>
#include <cuda_bf16.h>
#include <math.h>
#include <stdint.h>

#define NNODES 512
#define NEDGES 16384
#define LPN 20
#define TT 60
#define DD 128
#define H3 384
#define NGRU 21
#define GI_PER_G (NNODES*TT*H3)
#define LN_EPS 1e-5f

__device__ float g_GI[(size_t)NGRU * GI_PER_G];
__device__ float g_H[NGRU * NNODES * DD];
__device__ float g_cat[5 * NNODES * DD];
__device__ float g_bufA[NNODES * DD];
__device__ float g_bufB[NNODES * DD];
__device__ float g_bufC[NNODES * DD];
__device__ int   g_deg[NNODES];
__device__ float g_dinv[NNODES];
__device__ float g_logits[NNODES * 2];

__device__ __forceinline__ float sigmf_(float x) { return 1.f / (1.f + __expf(-x)); }
__device__ __forceinline__ float tanhf_(float x) {
    x = fminf(fmaxf(x, -15.f), 15.f);
    float e = __expf(2.f * x);
    return (e - 1.f) / (e + 1.f);
}

__device__ __forceinline__ void mma_bf16(float* d, const uint32_t* a, uint32_t b0, uint32_t b1) {
    asm volatile("mma.sync.aligned.m16n8k16.row.col.f32.bf16.bf16.f32 "
                 "{%0,%1,%2,%3}, {%4,%5,%6,%7}, {%8,%9}, {%0,%1,%2,%3};"
                 : "+f"(d[0]), "+f"(d[1]), "+f"(d[2]), "+f"(d[3])
                 : "r"(a[0]), "r"(a[1]), "r"(a[2]), "r"(a[3]), "r"(b0), "r"(b1));
}
// split two fp32 into packed bf16x2 hi and lo words (x = low half)
__device__ __forceinline__ void split2(float x, float y, uint32_t& hi, uint32_t& lo) {
    __nv_bfloat16 hx = __float2bfloat16(x);
    __nv_bfloat16 hy = __float2bfloat16(y);
    float rx = x - __bfloat162float(hx);
    float ry = y - __bfloat162float(hy);
    __nv_bfloat16 lx = __float2bfloat16(rx);
    __nv_bfloat16 ly = __float2bfloat16(ry);
    hi = ((uint32_t)__bfloat16_as_ushort(hy) << 16) | (uint32_t)__bfloat16_as_ushort(hx);
    lo = ((uint32_t)__bfloat16_as_ushort(ly) << 16) | (uint32_t)__bfloat16_as_ushort(lx);
}

// ---------------- Phase 1 (bf16x3 MMA): gi = x @ Wih^T + bih ---------------
// grid (240, 3, 21), 256 thr (8 warps, 2m x 4n), smem: 4 arrays [128][68] u32
#define PSTR 68
#define GI_SMEM (4 * 128 * PSTR * 4)
__global__ __launch_bounds__(256) void gi_bf16_kernel(
    const float* __restrict__ x_lp, const float* __restrict__ x_ns,
    const float* __restrict__ Wih_lp, const float* __restrict__ bih_lp,
    const float* __restrict__ Wih_ns, const float* __restrict__ bih_ns)
{
    extern __shared__ uint32_t su[];
    uint32_t* AHI = su;
    uint32_t* ALO = su + 128 * PSTR;
    uint32_t* BHI = su + 2 * 128 * PSTR;
    uint32_t* BLO = su + 3 * 128 * PSTR;
    const int g = blockIdx.z;
    const int mbase = blockIdx.x * 128;
    const int nbase = blockIdx.y * 128;
    const int tid = threadIdx.x;

    const float* W  = (g < LPN) ? (Wih_lp + (size_t)g * H3 * DD) : Wih_ns;
    const float* bi = (g < LPN) ? (bih_lp + g * H3) : bih_ns;
    const float* xp = (g < LPN) ? x_lp : x_ns;

    // fill A (x rows), split to bf16 hi/lo packed pairs
    for (int idx = tid; idx < 128 * 64; idx += 256) {
        int r = idx >> 6, j = idx & 63;
        int row = mbase + r;
        size_t off;
        if (g < LPN) {
            int n = row / TT, t = row - n * TT;
            off = (size_t)n * (LPN * TT * DD) + (size_t)g * (TT * DD) + (size_t)t * DD;
        } else off = (size_t)row * DD;
        float2 v = *reinterpret_cast<const float2*>(xp + off + 2 * j);
        uint32_t hi, lo;
        split2(v.x, v.y, hi, lo);
        AHI[r * PSTR + j] = hi;
        ALO[r * PSTR + j] = lo;
    }
    // fill B (Wih rows nbase..nbase+127)
    for (int idx = tid; idx < 128 * 64; idx += 256) {
        int r = idx >> 6, j = idx & 63;
        float2 v = *reinterpret_cast<const float2*>(W + (size_t)(nbase + r) * DD + 2 * j);
        uint32_t hi, lo;
        split2(v.x, v.y, hi, lo);
        BHI[r * PSTR + j] = hi;
        BLO[r * PSTR + j] = lo;
    }
    __syncthreads();

    const int wid = tid >> 5, lane = tid & 31;
    const int wm = wid & 1, wn = wid >> 1;     // warp tile 64 rows x 32 cols
    const int grp = lane >> 2, tig = lane & 3;

    float acc[4][4][4];
    #pragma unroll
    for (int mt = 0; mt < 4; mt++)
        #pragma unroll
        for (int nt = 0; nt < 4; nt++)
            #pragma unroll
            for (int q = 0; q < 4; q++) acc[mt][nt][q] = 0.f;

    #pragma unroll
    for (int kt = 0; kt < 8; kt++) {
        uint32_t ah[4][4], al[4][4];
        #pragma unroll
        for (int mt = 0; mt < 4; mt++) {
            int r0 = wm * 64 + mt * 16 + grp;
            ah[mt][0] = AHI[r0 * PSTR + kt * 8 + tig];
            ah[mt][1] = AHI[(r0 + 8) * PSTR + kt * 8 + tig];
            ah[mt][2] = AHI[r0 * PSTR + kt * 8 + 4 + tig];
            ah[mt][3] = AHI[(r0 + 8) * PSTR + kt * 8 + 4 + tig];
            al[mt][0] = ALO[r0 * PSTR + kt * 8 + tig];
            al[mt][1] = ALO[(r0 + 8) * PSTR + kt * 8 + tig];
            al[mt][2] = ALO[r0 * PSTR + kt * 8 + 4 + tig];
            al[mt][3] = ALO[(r0 + 8) * PSTR + kt * 8 + 4 + tig];
        }
        #pragma unroll
        for (int nt = 0; nt < 4; nt++) {
            int n0 = wn * 32 + nt * 8 + grp;
            uint32_t bh0 = BHI[n0 * PSTR + kt * 8 + tig];
            uint32_t bh1 = BHI[n0 * PSTR + kt * 8 + 4 + tig];
            uint32_t bl0 = BLO[n0 * PSTR + kt * 8 + tig];
            uint32_t bl1 = BLO[n0 * PSTR + kt * 8 + 4 + tig];
            #pragma unroll
            for (int mt = 0; mt < 4; mt++) {
                mma_bf16(acc[mt][nt], ah[mt], bh0, bh1);
                mma_bf16(acc[mt][nt], ah[mt], bl0, bl1);
                mma_bf16(acc[mt][nt], al[mt], bh0, bh1);
            }
        }
    }

    float* outp = g_GI + (size_t)g * GI_PER_G;
    #pragma unroll
    for (int nt = 0; nt < 4; nt++) {
        int cg = nbase + wn * 32 + nt * 8 + tig * 2;
        float b0 = bi[cg], b1 = bi[cg + 1];
        #pragma unroll
        for (int mt = 0; mt < 4; mt++) {
            int r0 = mbase + wm * 64 + mt * 16 + grp;
            *reinterpret_cast<float2*>(outp + (size_t)r0 * H3 + cg) =
                make_float2(acc[mt][nt][0] + b0, acc[mt][nt][1] + b1);
            *reinterpret_cast<float2*>(outp + (size_t)(r0 + 8) * H3 + cg) =
                make_float2(acc[mt][nt][2] + b0, acc[mt][nt][3] + b1);
        }
    }
}

// ---------------- Phase 2 (bf16x3 MMA recurrence) --------------------------
#define WSTR 68
#define SM_WHI 0
#define SM_WLO (384*WSTR)
#define SM_HHI (2*384*WSTR)
#define SM_HLO (2*384*WSTR + 32*WSTR)
#define GRU_SMEM ((2*384*WSTR + 2*32*WSTR) * 4)

__global__ __launch_bounds__(256) void gru_mma_kernel(
    const float* __restrict__ Whh_lp, const float* __restrict__ bhh_lp,
    const float* __restrict__ Whh_ns, const float* __restrict__ bhh_ns)
{
    extern __shared__ uint32_t su[];
    uint32_t* WHI = su + SM_WHI;
    uint32_t* WLO = su + SM_WLO;
    uint32_t* HHI = su + SM_HHI;
    uint32_t* HLO = su + SM_HLO;
    const int g = blockIdx.y;
    const int base = blockIdx.x * 32;
    const int tid = threadIdx.x;

    const float* Wp = (g < LPN) ? (Whh_lp + (size_t)g * H3 * DD) : Whh_ns;
    const float* bh = (g < LPN) ? (bhh_lp + g * H3) : bhh_ns;

    for (int idx = tid; idx < 384 * 64; idx += 256) {
        int n = idx >> 6, j = idx & 63;
        float2 wv = *reinterpret_cast<const float2*>(Wp + (size_t)n * DD + 2 * j);
        uint32_t hi, lo;
        split2(wv.x, wv.y, hi, lo);
        WHI[n * WSTR + j] = hi;
        WLO[n * WSTR + j] = lo;
    }
    for (int idx = tid; idx < 32 * WSTR; idx += 256) { HHI[idx] = 0u; HLO[idx] = 0u; }

    const int w = tid >> 5, lane = tid & 31;
    const int grp = lane >> 2, tig = lane & 3;

    float bias[3][4];
    #pragma unroll
    for (int gate = 0; gate < 3; gate++)
        #pragma unroll
        for (int cc = 0; cc < 4; cc++)
            bias[gate][cc] = bh[gate * 128 + w * 16 + (cc >> 1) * 8 + 2 * tig + (cc & 1)];

    int nrow[6];
    #pragma unroll
    for (int nt = 0; nt < 6; nt++)
        nrow[nt] = (nt >> 1) * 128 + w * 16 + (nt & 1) * 8 + grp;

    float hreg[4][4];
    #pragma unroll
    for (int mi = 0; mi < 4; mi++)
        #pragma unroll
        for (int cc = 0; cc < 4; cc++) hreg[mi][cc] = 0.f;

    __syncthreads();

    const float* gib = g_GI + (size_t)g * GI_PER_G;

    for (int t = 0; t < TT; t++) {
        float2 gi2[4][3][2];
        #pragma unroll
        for (int mi = 0; mi < 4; mi++) {
            int node = base + (mi >> 1) * 16 + (mi & 1) * 8 + grp;
            const float* rowp = gib + ((size_t)node * TT + t) * H3 + w * 16 + 2 * tig;
            #pragma unroll
            for (int gate = 0; gate < 3; gate++) {
                gi2[mi][gate][0] = *reinterpret_cast<const float2*>(rowp + gate * 128);
                gi2[mi][gate][1] = *reinterpret_cast<const float2*>(rowp + gate * 128 + 8);
            }
        }

        float acc[2][6][4];
        #pragma unroll
        for (int mt = 0; mt < 2; mt++)
            #pragma unroll
            for (int nt = 0; nt < 6; nt++)
                #pragma unroll
                for (int q = 0; q < 4; q++) acc[mt][nt][q] = 0.f;

        #pragma unroll
        for (int kt = 0; kt < 8; kt++) {
            uint32_t ahi[2][4], alo[2][4];
            #pragma unroll
            for (int mt = 0; mt < 2; mt++) {
                int r0 = mt * 16 + grp;
                ahi[mt][0] = HHI[r0 * WSTR + kt * 8 + tig];
                ahi[mt][1] = HHI[(r0 + 8) * WSTR + kt * 8 + tig];
                ahi[mt][2] = HHI[r0 * WSTR + kt * 8 + 4 + tig];
                ahi[mt][3] = HHI[(r0 + 8) * WSTR + kt * 8 + 4 + tig];
                alo[mt][0] = HLO[r0 * WSTR + kt * 8 + tig];
                alo[mt][1] = HLO[(r0 + 8) * WSTR + kt * 8 + tig];
                alo[mt][2] = HLO[r0 * WSTR + kt * 8 + 4 + tig];
                alo[mt][3] = HLO[(r0 + 8) * WSTR + kt * 8 + 4 + tig];
            }
            #pragma unroll
            for (int nt = 0; nt < 6; nt++) {
                uint32_t bh0 = WHI[nrow[nt] * WSTR + kt * 8 + tig];
                uint32_t bh1 = WHI[nrow[nt] * WSTR + kt * 8 + 4 + tig];
                uint32_t bl0 = WLO[nrow[nt] * WSTR + kt * 8 + tig];
                uint32_t bl1 = WLO[nrow[nt] * WSTR + kt * 8 + 4 + tig];
                #pragma unroll
                for (int mt = 0; mt < 2; mt++) {
                    mma_bf16(acc[mt][nt], ahi[mt], bh0, bh1);
                    mma_bf16(acc[mt][nt], ahi[mt], bl0, bl1);
                    mma_bf16(acc[mt][nt], alo[mt], bh0, bh1);
                }
            }
        }
        __syncthreads();

        #pragma unroll
        for (int mt = 0; mt < 2; mt++)
            #pragma unroll
            for (int rh = 0; rh < 2; rh++) {
                int mi = mt * 2 + rh;
                #pragma unroll
                for (int hf = 0; hf < 2; hf++)
                    #pragma unroll
                    for (int cl = 0; cl < 2; cl++) {
                        int q = rh * 2 + cl;
                        int cc = hf * 2 + cl;
                        float gr = cl ? gi2[mi][0][hf].y : gi2[mi][0][hf].x;
                        float gz = cl ? gi2[mi][1][hf].y : gi2[mi][1][hf].x;
                        float gn = cl ? gi2[mi][2][hf].y : gi2[mi][2][hf].x;
                        float r = sigmf_(gr + acc[mt][0 + hf][q] + bias[0][cc]);
                        float z = sigmf_(gz + acc[mt][2 + hf][q] + bias[1][cc]);
                        float nn = tanhf_(gn + r * (acc[mt][4 + hf][q] + bias[2][cc]));
                        hreg[mi][cc] = (1.f - z) * nn + z * hreg[mi][cc];
                    }
            }
        #pragma unroll
        for (int mi = 0; mi < 4; mi++) {
            int row = (mi >> 1) * 16 + (mi & 1) * 8 + grp;
            uint32_t hi0, lo0, hi1, lo1;
            split2(hreg[mi][0], hreg[mi][1], hi0, lo0);
            split2(hreg[mi][2], hreg[mi][3], hi1, lo1);
            HHI[row * WSTR + w * 8 + tig] = hi0;
            HLO[row * WSTR + w * 8 + tig] = lo0;
            HHI[row * WSTR + w * 8 + 4 + tig] = hi1;
            HLO[row * WSTR + w * 8 + 4 + tig] = lo1;
        }
        __syncthreads();
    }

    #pragma unroll
    for (int mi = 0; mi < 4; mi++) {
        int node = base + (mi >> 1) * 16 + (mi & 1) * 8 + grp;
        float* op = g_H + ((size_t)g * NNODES + node) * DD + w * 16;
        #pragma unroll
        for (int cc = 0; cc < 4; cc++)
            op[(cc >> 1) * 8 + 2 * tig + (cc & 1)] = hreg[mi][cc];
    }
}

// ---------------- tail kernels ----------------
__global__ void gemm_tn_kernel(const float* __restrict__ A, int lda,
                               const float* __restrict__ B, int ldb,
                               const float* __restrict__ bias,
                               float* __restrict__ C, int ldc,
                               int M, int N, int K)
{
    __shared__ float As[32 * 32];
    __shared__ float Bs[32 * 33];
    const int rbase = blockIdx.x * 32;
    const int cbase = blockIdx.y * 32;
    const int tid = threadIdx.x;
    const int ty = tid >> 5, tx = tid & 31;

    float acc[4] = {0.f, 0.f, 0.f, 0.f};
    for (int kb = 0; kb < K; kb += 32) {
        #pragma unroll
        for (int i = 0; i < 4; i++) {
            int idx = tid + i * 256;
            int r = idx >> 5, kk = idx & 31;
            As[r * 32 + kk] = A[(size_t)(rbase + r) * lda + kb + kk];
            Bs[r * 33 + kk] = (cbase + r < N) ? B[(size_t)(cbase + r) * ldb + kb + kk] : 0.f;
        }
        __syncthreads();
        #pragma unroll
        for (int kk = 0; kk < 32; kk++) {
            float bv = Bs[tx * 33 + kk];
            #pragma unroll
            for (int i = 0; i < 4; i++)
                acc[i] += As[(ty + 8 * i) * 32 + kk] * bv;
        }
        __syncthreads();
    }
    if (cbase + tx < N) {
        float bb = bias ? bias[cbase + tx] : 0.f;
        #pragma unroll
        for (int i = 0; i < 4; i++)
            C[(size_t)(rbase + ty + 8 * i) * ldc + cbase + tx] = acc[i] + bb;
    }
}

__global__ void build_cat_kernel(const float* __restrict__ x_pdt,
                                 const float* __restrict__ x_ref,
                                 const float* __restrict__ x_def)
{
    int i = blockIdx.x * 256 + threadIdx.x;
    g_cat[i] = x_pdt[i];
    g_cat[NNODES * DD + i] = x_ref[i];
    g_cat[2 * NNODES * DD + i] = x_def[i];
    g_cat[4 * NNODES * DD + i] = g_H[(size_t)LPN * NNODES * DD + i];
}

__global__ void deg_init_kernel() {
    int i = blockIdx.x * 256 + threadIdx.x;
    if (i < NNODES) g_deg[i] = 1;
}
__global__ void deg_edge_kernel(const int* __restrict__ ei) {
    int e = blockIdx.x * 256 + threadIdx.x;
    if (e < NEDGES) atomicAdd(&g_deg[ei[NEDGES + e]], 1);
}
__global__ void dinv_kernel() {
    int i = blockIdx.x * 256 + threadIdx.x;
    if (i < NNODES) g_dinv[i] = rsqrtf((float)g_deg[i]);
}
__global__ void agg_init_kernel(const float* __restrict__ xw,
                                const float* __restrict__ bias,
                                float* __restrict__ out)
{
    int i = blockIdx.x * 256 + threadIdx.x;
    int n = i >> 7, d = i & 127;
    float di = g_dinv[n];
    out[i] = bias[d] + di * di * xw[i];
}
__global__ void agg_edge_kernel(const float* __restrict__ xw,
                                const int* __restrict__ ei,
                                float* __restrict__ out)
{
    int i = blockIdx.x * 256 + threadIdx.x;
    int e = i >> 7, d = i & 127;
    int s = ei[e], t = ei[NEDGES + e];
    atomicAdd(&out[t * 128 + d], xw[s * 128 + d] * g_dinv[s] * g_dinv[t]);
}
__global__ void relu_ln_kernel(const float* __restrict__ in,
                               const float* __restrict__ gam,
                               const float* __restrict__ bet,
                               float* __restrict__ out)
{
    int row = blockIdx.x, d = threadIdx.x;
    float v = fmaxf(in[row * 128 + d], 0.f);
    float s = v, sq = v * v;
    #pragma unroll
    for (int o = 16; o > 0; o >>= 1) {
        s  += __shfl_xor_sync(0xffffffffu, s, o);
        sq += __shfl_xor_sync(0xffffffffu, sq, o);
    }
    __shared__ float ss[4], ssq[4];
    int w = d >> 5, l = d & 31;
    if (l == 0) { ss[w] = s; ssq[w] = sq; }
    __syncthreads();
    float st = ss[0] + ss[1] + ss[2] + ss[3];
    float sqt = ssq[0] + ssq[1] + ssq[2] + ssq[3];
    float m = st * (1.f / 128.f);
    float var = sqt * (1.f / 128.f) - m * m;
    out[row * 128 + d] = (v - m) * rsqrtf(var + LN_EPS) * gam[d] + bet[d];
}
__global__ void relu_kernel(const float* __restrict__ in, float* __restrict__ out) {
    int i = blockIdx.x * 256 + threadIdx.x;
    if (i < NNODES * DD) out[i] = fmaxf(in[i], 0.f);
}
__global__ void logsoftmax_kernel(float* __restrict__ out) {
    int i = blockIdx.x * 256 + threadIdx.x;
    if (i < NNODES) {
        float a = g_logits[2 * i], b = g_logits[2 * i + 1];
        float m = fmaxf(a, b);
        float lse = m + logf(expf(a - m) + expf(b - m));
        out[2 * i] = a - lse;
        out[2 * i + 1] = b - lse;
    }
}

extern "C" void kernel_launch(void* const* d_in, const int* in_sizes, int n_in,
                              void* d_out, int out_size)
{
    const float* x_lp    = (const float*)d_in[0];
    const float* x_ns    = (const float*)d_in[1];
    const float* x_ref   = (const float*)d_in[2];
    const float* x_def   = (const float*)d_in[3];
    const float* x_pdt   = (const float*)d_in[4];
    const int*   edge    = (const int*)  d_in[5];
    const float* Wih_lp  = (const float*)d_in[6];
    const float* Whh_lp  = (const float*)d_in[7];
    const float* bih_lp  = (const float*)d_in[8];
    const float* bhh_lp  = (const float*)d_in[9];
    const float* lp_fc_W = (const float*)d_in[10];
    const float* lp_fc_b = (const float*)d_in[11];
    const float* Wih_ns  = (const float*)d_in[12];
    const float* Whh_ns  = (const float*)d_in[13];
    const float* bih_ns  = (const float*)d_in[14];
    const float* bhh_ns  = (const float*)d_in[15];
    const float* all_fc_W = (const float*)d_in[16];
    const float* all_fc_b = (const float*)d_in[17];
    const float* convW[3] = {(const float*)d_in[18], (const float*)d_in[20], (const float*)d_in[22]};
    const float* convB[3] = {(const float*)d_in[19], (const float*)d_in[21], (const float*)d_in[23]};
    const float* lnG[2] = {(const float*)d_in[24], (const float*)d_in[26]};
    const float* lnB[2] = {(const float*)d_in[25], (const float*)d_in[27]};
    const float* mp1_W = (const float*)d_in[28];
    const float* mp1_b = (const float*)d_in[29];
    const float* mp2_W = (const float*)d_in[30];
    const float* mp2_b = (const float*)d_in[31];
    float* out = (float*)d_out;
    (void)in_sizes; (void)n_in; (void)out_size;

    float *H, *cat, *bufA, *bufB, *bufC, *logits;
    cudaGetSymbolAddress((void**)&H, g_H);
    cudaGetSymbolAddress((void**)&cat, g_cat);
    cudaGetSymbolAddress((void**)&bufA, g_bufA);
    cudaGetSymbolAddress((void**)&bufB, g_bufB);
    cudaGetSymbolAddress((void**)&bufC, g_bufC);
    cudaGetSymbolAddress((void**)&logits, g_logits);

    cudaFuncSetAttribute(gi_bf16_kernel, cudaFuncAttributeMaxDynamicSharedMemorySize, GI_SMEM);
    cudaFuncSetAttribute(gru_mma_kernel, cudaFuncAttributeMaxDynamicSharedMemorySize, GRU_SMEM);

    // tiny kernels first so capture slot (launch idx 3) lands on gi_bf16_kernel
    deg_init_kernel<<<2, 256>>>();
    deg_edge_kernel<<<NEDGES / 256, 256>>>(edge);
    dinv_kernel<<<2, 256>>>();
    gi_bf16_kernel<<<dim3(240, 3, NGRU), 256, GI_SMEM>>>(x_lp, x_ns, Wih_lp, bih_lp, Wih_ns, bih_ns);
    gru_mma_kernel<<<dim3(16, NGRU), 256, GRU_SMEM>>>(Whh_lp, bhh_lp, Whh_ns, bhh_ns);

    gemm_tn_kernel<<<dim3(16, 4), 256>>>(H, LPN * DD, lp_fc_W, LPN * DD, lp_fc_b,
                                         cat + 3 * NNODES * DD, DD, NNODES, DD, LPN * DD);
    build_cat_kernel<<<256, 256>>>(x_pdt, x_ref, x_def);
    gemm_tn_kernel<<<dim3(16, 4), 256>>>(cat, 5 * DD, all_fc_W, 5 * DD, all_fc_b,
                                         bufA, DD, NNODES, DD, 5 * DD);

    // conv0
    gemm_tn_kernel<<<dim3(16, 4), 256>>>(bufA, DD, convW[0], DD, nullptr, bufB, DD, NNODES, DD, DD);
    agg_init_kernel<<<256, 256>>>(bufB, convB[0], bufC);
    agg_edge_kernel<<<NEDGES * DD / 256, 256>>>(bufB, edge, bufC);
    relu_ln_kernel<<<NNODES, 128>>>(bufC, lnG[0], lnB[0], bufA);
    // conv1
    gemm_tn_kernel<<<dim3(16, 4), 256>>>(bufA, DD, convW[1], DD, nullptr, bufB, DD, NNODES, DD, DD);
    agg_init_kernel<<<256, 256>>>(bufB, convB[1], bufC);
    agg_edge_kernel<<<NEDGES * DD / 256, 256>>>(bufB, edge, bufC);
    relu_ln_kernel<<<NNODES, 128>>>(bufC, lnG[1], lnB[1], bufA);
    // conv2 -> emb straight to d_out[0:65536]
    gemm_tn_kernel<<<dim3(16, 4), 256>>>(bufA, DD, convW[2], DD, nullptr, bufB, DD, NNODES, DD, DD);
    agg_init_kernel<<<256, 256>>>(bufB, convB[2], out);
    agg_edge_kernel<<<NEDGES * DD / 256, 256>>>(bufB, edge, out);
    relu_kernel<<<256, 256>>>(out, bufA);
    // mp1, mp2
    gemm_tn_kernel<<<dim3(16, 4), 256>>>(bufA, DD, mp1_W, DD, mp1_b, bufB, DD, NNODES, DD, DD);
    gemm_tn_kernel<<<dim3(16, 1), 256>>>(bufB, DD, mp2_W, DD, mp2_b, logits, 2, NNODES, 2, DD);
    logsoftmax_kernel<<<2, 256>>>(out + NNODES * DD);
}

// round 8
// speedup vs baseline: 1.9201x; 1.1370x over previous
#include <cuda_runtime.h>
#include <cuda_bf16.h>
#include <math.h>
#include <stdint.h>

#define NNODES 512
#define NEDGES 16384
#define LPN 20
#define TT 60
#define DD 128
#define H3 384
#define NGRU 21
#define GI_PER_G (NNODES*TT*H3)
#define LN_EPS 1e-5f

__device__ float g_GI[(size_t)NGRU * GI_PER_G];
__device__ float g_H[NGRU * NNODES * DD];
__device__ float g_cat[5 * NNODES * DD];
__device__ float g_bufA[NNODES * DD];
__device__ float g_bufB[NNODES * DD];
__device__ float g_bufC[NNODES * DD];
__device__ int   g_deg[NNODES];
__device__ float g_dinv[NNODES];
__device__ float g_logits[NNODES * 2];
__device__ uint32_t g_WHI[NGRU * H3 * 64];
__device__ uint32_t g_WLO[NGRU * H3 * 64];

__device__ __forceinline__ float sigmf_(float x) { return 1.f / (1.f + __expf(-x)); }
__device__ __forceinline__ float tanhf_(float x) {
    x = fminf(fmaxf(x, -15.f), 15.f);
    float e = __expf(2.f * x);
    return (e - 1.f) / (e + 1.f);
}

__device__ __forceinline__ void mma_bf16(float* d, const uint32_t* a, uint32_t b0, uint32_t b1) {
    asm volatile("mma.sync.aligned.m16n8k16.row.col.f32.bf16.bf16.f32 "
                 "{%0,%1,%2,%3}, {%4,%5,%6,%7}, {%8,%9}, {%0,%1,%2,%3};"
                 : "+f"(d[0]), "+f"(d[1]), "+f"(d[2]), "+f"(d[3])
                 : "r"(a[0]), "r"(a[1]), "r"(a[2]), "r"(a[3]), "r"(b0), "r"(b1));
}
__device__ __forceinline__ void split2(float x, float y, uint32_t& hi, uint32_t& lo) {
    __nv_bfloat16 hx = __float2bfloat16(x);
    __nv_bfloat16 hy = __float2bfloat16(y);
    float rx = x - __bfloat162float(hx);
    float ry = y - __bfloat162float(hy);
    __nv_bfloat16 lx = __float2bfloat16(rx);
    __nv_bfloat16 ly = __float2bfloat16(ry);
    hi = ((uint32_t)__bfloat16_as_ushort(hy) << 16) | (uint32_t)__bfloat16_as_ushort(hx);
    lo = ((uint32_t)__bfloat16_as_ushort(ly) << 16) | (uint32_t)__bfloat16_as_ushort(lx);
}

// ---------------- prepass: split all Wih into bf16 hi/lo ----------------
__global__ void wsplit_kernel(const float* __restrict__ Wih_lp,
                              const float* __restrict__ Wih_ns)
{
    int idx = blockIdx.x * 256 + threadIdx.x;       // < 21*384*64
    if (idx >= NGRU * H3 * 64) return;
    int g = idx / (H3 * 64);
    int rem = idx - g * H3 * 64;
    int n = rem >> 6, j = rem & 63;
    const float* W = (g < LPN) ? (Wih_lp + (size_t)g * H3 * DD) : Wih_ns;
    float2 v = *reinterpret_cast<const float2*>(W + (size_t)n * DD + 2 * j);
    uint32_t hi, lo;
    split2(v.x, v.y, hi, lo);
    g_WHI[idx] = hi;
    g_WLO[idx] = lo;
}

// ---------------- Phase 1 (bf16x3 MMA): gi = x @ Wih^T + bih ---------------
// grid (480, 21): M=64 rows per CTA, loops over 3 N-tiles of 128.
// smem: AHI/ALO [64][68], BHI/BLO [128][68] u32 = 104448 B -> 2 CTAs/SM
#define PSTR 68
#define GI_SMEM ((2*64*PSTR + 2*128*PSTR) * 4)
__global__ __launch_bounds__(256, 2) void gi_bf16_kernel(
    const float* __restrict__ x_lp, const float* __restrict__ x_ns,
    const float* __restrict__ bih_lp, const float* __restrict__ bih_ns)
{
    extern __shared__ uint32_t su[];
    uint32_t* AHI = su;
    uint32_t* ALO = su + 64 * PSTR;
    uint32_t* BHI = su + 2 * 64 * PSTR;
    uint32_t* BLO = su + 2 * 64 * PSTR + 128 * PSTR;
    const int g = blockIdx.y;
    const int mbase = blockIdx.x * 64;
    const int tid = threadIdx.x;

    const float* bi = (g < LPN) ? (bih_lp + g * H3) : bih_ns;
    const float* xp = (g < LPN) ? x_lp : x_ns;

    // fill A once (split fp32 -> bf16 hi/lo)
    for (int idx = tid; idx < 64 * 64; idx += 256) {
        int r = idx >> 6, j = idx & 63;
        int row = mbase + r;
        size_t off;
        if (g < LPN) {
            int n = row / TT, t = row - n * TT;
            off = (size_t)n * (LPN * TT * DD) + (size_t)g * (TT * DD) + (size_t)t * DD;
        } else off = (size_t)row * DD;
        float2 v = *reinterpret_cast<const float2*>(xp + off + 2 * j);
        uint32_t hi, lo;
        split2(v.x, v.y, hi, lo);
        AHI[r * PSTR + j] = hi;
        ALO[r * PSTR + j] = lo;
    }

    const int wid = tid >> 5, lane = tid & 31;
    const int wm = wid & 1, wn = wid >> 1;     // warp tile: 32 rows x 32 cols
    const int grp = lane >> 2, tig = lane & 3;

    float* outp = g_GI + (size_t)g * GI_PER_G;
    const uint32_t* wsrc_hi = g_WHI + (size_t)g * H3 * 64;
    const uint32_t* wsrc_lo = g_WLO + (size_t)g * H3 * 64;

    for (int nb = 0; nb < 3; nb++) {
        const int nbase = nb * 128;
        // fill B (pure copy of pre-split W)
        for (int idx = tid; idx < 128 * 64; idx += 256) {
            int r = idx >> 6, j = idx & 63;
            BHI[r * PSTR + j] = wsrc_hi[(size_t)(nbase + r) * 64 + j];
            BLO[r * PSTR + j] = wsrc_lo[(size_t)(nbase + r) * 64 + j];
        }
        __syncthreads();

        float acc[2][4][4];
        #pragma unroll
        for (int mt = 0; mt < 2; mt++)
            #pragma unroll
            for (int nt = 0; nt < 4; nt++)
                #pragma unroll
                for (int q = 0; q < 4; q++) acc[mt][nt][q] = 0.f;

        #pragma unroll
        for (int kt = 0; kt < 8; kt++) {
            uint32_t ah[2][4], al[2][4];
            #pragma unroll
            for (int mt = 0; mt < 2; mt++) {
                int r0 = wm * 32 + mt * 16 + grp;
                ah[mt][0] = AHI[r0 * PSTR + kt * 8 + tig];
                ah[mt][1] = AHI[(r0 + 8) * PSTR + kt * 8 + tig];
                ah[mt][2] = AHI[r0 * PSTR + kt * 8 + 4 + tig];
                ah[mt][3] = AHI[(r0 + 8) * PSTR + kt * 8 + 4 + tig];
                al[mt][0] = ALO[r0 * PSTR + kt * 8 + tig];
                al[mt][1] = ALO[(r0 + 8) * PSTR + kt * 8 + tig];
                al[mt][2] = ALO[r0 * PSTR + kt * 8 + 4 + tig];
                al[mt][3] = ALO[(r0 + 8) * PSTR + kt * 8 + 4 + tig];
            }
            #pragma unroll
            for (int nt = 0; nt < 4; nt++) {
                int n0 = wn * 32 + nt * 8 + grp;
                uint32_t bh0 = BHI[n0 * PSTR + kt * 8 + tig];
                uint32_t bh1 = BHI[n0 * PSTR + kt * 8 + 4 + tig];
                uint32_t bl0 = BLO[n0 * PSTR + kt * 8 + tig];
                uint32_t bl1 = BLO[n0 * PSTR + kt * 8 + 4 + tig];
                #pragma unroll
                for (int mt = 0; mt < 2; mt++) {
                    mma_bf16(acc[mt][nt], ah[mt], bh0, bh1);
                    mma_bf16(acc[mt][nt], ah[mt], bl0, bl1);
                    mma_bf16(acc[mt][nt], al[mt], bh0, bh1);
                }
            }
        }

        #pragma unroll
        for (int nt = 0; nt < 4; nt++) {
            int cg = nbase + wn * 32 + nt * 8 + tig * 2;
            float b0 = bi[cg], b1 = bi[cg + 1];
            #pragma unroll
            for (int mt = 0; mt < 2; mt++) {
                int r0 = mbase + wm * 32 + mt * 16 + grp;
                *reinterpret_cast<float2*>(outp + (size_t)r0 * H3 + cg) =
                    make_float2(acc[mt][nt][0] + b0, acc[mt][nt][1] + b1);
                *reinterpret_cast<float2*>(outp + (size_t)(r0 + 8) * H3 + cg) =
                    make_float2(acc[mt][nt][2] + b0, acc[mt][nt][3] + b1);
            }
        }
        __syncthreads();   // before next B fill overwrites
    }
}

// ---------------- Phase 2 (bf16x3 MMA recurrence) --------------------------
#define WSTR 68
#define SM_WHI 0
#define SM_WLO (384*WSTR)
#define SM_HHI (2*384*WSTR)
#define SM_HLO (2*384*WSTR + 32*WSTR)
#define GRU_SMEM ((2*384*WSTR + 2*32*WSTR) * 4)

__global__ __launch_bounds__(256) void gru_mma_kernel(
    const float* __restrict__ Whh_lp, const float* __restrict__ bhh_lp,
    const float* __restrict__ Whh_ns, const float* __restrict__ bhh_ns)
{
    extern __shared__ uint32_t su[];
    uint32_t* WHI = su + SM_WHI;
    uint32_t* WLO = su + SM_WLO;
    uint32_t* HHI = su + SM_HHI;
    uint32_t* HLO = su + SM_HLO;
    const int g = blockIdx.y;
    const int base = blockIdx.x * 32;
    const int tid = threadIdx.x;

    const float* Wp = (g < LPN) ? (Whh_lp + (size_t)g * H3 * DD) : Whh_ns;
    const float* bh = (g < LPN) ? (bhh_lp + g * H3) : bhh_ns;

    for (int idx = tid; idx < 384 * 64; idx += 256) {
        int n = idx >> 6, j = idx & 63;
        float2 wv = *reinterpret_cast<const float2*>(Wp + (size_t)n * DD + 2 * j);
        uint32_t hi, lo;
        split2(wv.x, wv.y, hi, lo);
        WHI[n * WSTR + j] = hi;
        WLO[n * WSTR + j] = lo;
    }
    for (int idx = tid; idx < 32 * WSTR; idx += 256) { HHI[idx] = 0u; HLO[idx] = 0u; }

    const int w = tid >> 5, lane = tid & 31;
    const int grp = lane >> 2, tig = lane & 3;

    float bias[3][4];
    #pragma unroll
    for (int gate = 0; gate < 3; gate++)
        #pragma unroll
        for (int cc = 0; cc < 4; cc++)
            bias[gate][cc] = bh[gate * 128 + w * 16 + (cc >> 1) * 8 + 2 * tig + (cc & 1)];

    int nrow[6];
    #pragma unroll
    for (int nt = 0; nt < 6; nt++)
        nrow[nt] = (nt >> 1) * 128 + w * 16 + (nt & 1) * 8 + grp;

    float hreg[4][4];
    #pragma unroll
    for (int mi = 0; mi < 4; mi++)
        #pragma unroll
        for (int cc = 0; cc < 4; cc++) hreg[mi][cc] = 0.f;

    __syncthreads();

    const float* gib = g_GI + (size_t)g * GI_PER_G;

    for (int t = 0; t < TT; t++) {
        float2 gi2[4][3][2];
        #pragma unroll
        for (int mi = 0; mi < 4; mi++) {
            int node = base + (mi >> 1) * 16 + (mi & 1) * 8 + grp;
            const float* rowp = gib + ((size_t)node * TT + t) * H3 + w * 16 + 2 * tig;
            #pragma unroll
            for (int gate = 0; gate < 3; gate++) {
                gi2[mi][gate][0] = *reinterpret_cast<const float2*>(rowp + gate * 128);
                gi2[mi][gate][1] = *reinterpret_cast<const float2*>(rowp + gate * 128 + 8);
            }
        }

        float acc[2][6][4];
        #pragma unroll
        for (int mt = 0; mt < 2; mt++)
            #pragma unroll
            for (int nt = 0; nt < 6; nt++)
                #pragma unroll
                for (int q = 0; q < 4; q++) acc[mt][nt][q] = 0.f;

        #pragma unroll
        for (int kt = 0; kt < 8; kt++) {
            uint32_t ahi[2][4], alo[2][4];
            #pragma unroll
            for (int mt = 0; mt < 2; mt++) {
                int r0 = mt * 16 + grp;
                ahi[mt][0] = HHI[r0 * WSTR + kt * 8 + tig];
                ahi[mt][1] = HHI[(r0 + 8) * WSTR + kt * 8 + tig];
                ahi[mt][2] = HHI[r0 * WSTR + kt * 8 + 4 + tig];
                ahi[mt][3] = HHI[(r0 + 8) * WSTR + kt * 8 + 4 + tig];
                alo[mt][0] = HLO[r0 * WSTR + kt * 8 + tig];
                alo[mt][1] = HLO[(r0 + 8) * WSTR + kt * 8 + tig];
                alo[mt][2] = HLO[r0 * WSTR + kt * 8 + 4 + tig];
                alo[mt][3] = HLO[(r0 + 8) * WSTR + kt * 8 + 4 + tig];
            }
            #pragma unroll
            for (int nt = 0; nt < 6; nt++) {
                uint32_t bh0 = WHI[nrow[nt] * WSTR + kt * 8 + tig];
                uint32_t bh1 = WHI[nrow[nt] * WSTR + kt * 8 + 4 + tig];
                uint32_t bl0 = WLO[nrow[nt] * WSTR + kt * 8 + tig];
                uint32_t bl1 = WLO[nrow[nt] * WSTR + kt * 8 + 4 + tig];
                #pragma unroll
                for (int mt = 0; mt < 2; mt++) {
                    mma_bf16(acc[mt][nt], ahi[mt], bh0, bh1);
                    mma_bf16(acc[mt][nt], ahi[mt], bl0, bl1);
                    mma_bf16(acc[mt][nt], alo[mt], bh0, bh1);
                }
            }
        }
        __syncthreads();

        #pragma unroll
        for (int mt = 0; mt < 2; mt++)
            #pragma unroll
            for (int rh = 0; rh < 2; rh++) {
                int mi = mt * 2 + rh;
                #pragma unroll
                for (int hf = 0; hf < 2; hf++)
                    #pragma unroll
                    for (int cl = 0; cl < 2; cl++) {
                        int q = rh * 2 + cl;
                        int cc = hf * 2 + cl;
                        float gr = cl ? gi2[mi][0][hf].y : gi2[mi][0][hf].x;
                        float gz = cl ? gi2[mi][1][hf].y : gi2[mi][1][hf].x;
                        float gn = cl ? gi2[mi][2][hf].y : gi2[mi][2][hf].x;
                        float r = sigmf_(gr + acc[mt][0 + hf][q] + bias[0][cc]);
                        float z = sigmf_(gz + acc[mt][2 + hf][q] + bias[1][cc]);
                        float nn = tanhf_(gn + r * (acc[mt][4 + hf][q] + bias[2][cc]));
                        hreg[mi][cc] = (1.f - z) * nn + z * hreg[mi][cc];
                    }
            }
        #pragma unroll
        for (int mi = 0; mi < 4; mi++) {
            int row = (mi >> 1) * 16 + (mi & 1) * 8 + grp;
            uint32_t hi0, lo0, hi1, lo1;
            split2(hreg[mi][0], hreg[mi][1], hi0, lo0);
            split2(hreg[mi][2], hreg[mi][3], hi1, lo1);
            HHI[row * WSTR + w * 8 + tig] = hi0;
            HLO[row * WSTR + w * 8 + tig] = lo0;
            HHI[row * WSTR + w * 8 + 4 + tig] = hi1;
            HLO[row * WSTR + w * 8 + 4 + tig] = lo1;
        }
        __syncthreads();
    }

    #pragma unroll
    for (int mi = 0; mi < 4; mi++) {
        int node = base + (mi >> 1) * 16 + (mi & 1) * 8 + grp;
        float* op = g_H + ((size_t)g * NNODES + node) * DD + w * 16;
        #pragma unroll
        for (int cc = 0; cc < 4; cc++)
            op[(cc >> 1) * 8 + 2 * tig + (cc & 1)] = hreg[mi][cc];
    }
}

// ---------------- tail kernels ----------------
__global__ void gemm_tn_kernel(const float* __restrict__ A, int lda,
                               const float* __restrict__ B, int ldb,
                               const float* __restrict__ bias,
                               float* __restrict__ C, int ldc,
                               int M, int N, int K)
{
    __shared__ float As[32 * 32];
    __shared__ float Bs[32 * 33];
    const int rbase = blockIdx.x * 32;
    const int cbase = blockIdx.y * 32;
    const int tid = threadIdx.x;
    const int ty = tid >> 5, tx = tid & 31;

    float acc[4] = {0.f, 0.f, 0.f, 0.f};
    for (int kb = 0; kb < K; kb += 32) {
        #pragma unroll
        for (int i = 0; i < 4; i++) {
            int idx = tid + i * 256;
            int r = idx >> 5, kk = idx & 31;
            As[r * 32 + kk] = A[(size_t)(rbase + r) * lda + kb + kk];
            Bs[r * 33 + kk] = (cbase + r < N) ? B[(size_t)(cbase + r) * ldb + kb + kk] : 0.f;
        }
        __syncthreads();
        #pragma unroll
        for (int kk = 0; kk < 32; kk++) {
            float bv = Bs[tx * 33 + kk];
            #pragma unroll
            for (int i = 0; i < 4; i++)
                acc[i] += As[(ty + 8 * i) * 32 + kk] * bv;
        }
        __syncthreads();
    }
    if (cbase + tx < N) {
        float bb = bias ? bias[cbase + tx] : 0.f;
        #pragma unroll
        for (int i = 0; i < 4; i++)
            C[(size_t)(rbase + ty + 8 * i) * ldc + cbase + tx] = acc[i] + bb;
    }
}

__global__ void build_cat_kernel(const float* __restrict__ x_pdt,
                                 const float* __restrict__ x_ref,
                                 const float* __restrict__ x_def)
{
    int i = blockIdx.x * 256 + threadIdx.x;
    g_cat[i] = x_pdt[i];
    g_cat[NNODES * DD + i] = x_ref[i];
    g_cat[2 * NNODES * DD + i] = x_def[i];
    g_cat[4 * NNODES * DD + i] = g_H[(size_t)LPN * NNODES * DD + i];
}

__global__ void deg_init_kernel() {
    int i = blockIdx.x * 256 + threadIdx.x;
    if (i < NNODES) g_deg[i] = 1;
}
__global__ void deg_edge_kernel(const int* __restrict__ ei) {
    int e = blockIdx.x * 256 + threadIdx.x;
    if (e < NEDGES) atomicAdd(&g_deg[ei[NEDGES + e]], 1);
}
__global__ void dinv_kernel() {
    int i = blockIdx.x * 256 + threadIdx.x;
    if (i < NNODES) g_dinv[i] = rsqrtf((float)g_deg[i]);
}
__global__ void agg_init_kernel(const float* __restrict__ xw,
                                const float* __restrict__ bias,
                                float* __restrict__ out)
{
    int i = blockIdx.x * 256 + threadIdx.x;
    int n = i >> 7, d = i & 127;
    float di = g_dinv[n];
    out[i] = bias[d] + di * di * xw[i];
}
__global__ void agg_edge_kernel(const float* __restrict__ xw,
                                const int* __restrict__ ei,
                                float* __restrict__ out)
{
    int i = blockIdx.x * 256 + threadIdx.x;
    int e = i >> 7, d = i & 127;
    int s = ei[e], t = ei[NEDGES + e];
    atomicAdd(&out[t * 128 + d], xw[s * 128 + d] * g_dinv[s] * g_dinv[t]);
}
__global__ void relu_ln_kernel(const float* __restrict__ in,
                               const float* __restrict__ gam,
                               const float* __restrict__ bet,
                               float* __restrict__ out)
{
    int row = blockIdx.x, d = threadIdx.x;
    float v = fmaxf(in[row * 128 + d], 0.f);
    float s = v, sq = v * v;
    #pragma unroll
    for (int o = 16; o > 0; o >>= 1) {
        s  += __shfl_xor_sync(0xffffffffu, s, o);
        sq += __shfl_xor_sync(0xffffffffu, sq, o);
    }
    __shared__ float ss[4], ssq[4];
    int w = d >> 5, l = d & 31;
    if (l == 0) { ss[w] = s; ssq[w] = sq; }
    __syncthreads();
    float st = ss[0] + ss[1] + ss[2] + ss[3];
    float sqt = ssq[0] + ssq[1] + ssq[2] + ssq[3];
    float m = st * (1.f / 128.f);
    float var = sqt * (1.f / 128.f) - m * m;
    out[row * 128 + d] = (v - m) * rsqrtf(var + LN_EPS) * gam[d] + bet[d];
}
__global__ void relu_kernel(const float* __restrict__ in, float* __restrict__ out) {
    int i = blockIdx.x * 256 + threadIdx.x;
    if (i < NNODES * DD) out[i] = fmaxf(in[i], 0.f);
}
__global__ void logsoftmax_kernel(float* __restrict__ out) {
    int i = blockIdx.x * 256 + threadIdx.x;
    if (i < NNODES) {
        float a = g_logits[2 * i], b = g_logits[2 * i + 1];
        float m = fmaxf(a, b);
        float lse = m + logf(expf(a - m) + expf(b - m));
        out[2 * i] = a - lse;
        out[2 * i + 1] = b - lse;
    }
}

extern "C" void kernel_launch(void* const* d_in, const int* in_sizes, int n_in,
                              void* d_out, int out_size)
{
    const float* x_lp    = (const float*)d_in[0];
    const float* x_ns    = (const float*)d_in[1];
    const float* x_ref   = (const float*)d_in[2];
    const float* x_def   = (const float*)d_in[3];
    const float* x_pdt   = (const float*)d_in[4];
    const int*   edge    = (const int*)  d_in[5];
    const float* Wih_lp  = (const float*)d_in[6];
    const float* Whh_lp  = (const float*)d_in[7];
    const float* bih_lp  = (const float*)d_in[8];
    const float* bhh_lp  = (const float*)d_in[9];
    const float* lp_fc_W = (const float*)d_in[10];
    const float* lp_fc_b = (const float*)d_in[11];
    const float* Wih_ns  = (const float*)d_in[12];
    const float* Whh_ns  = (const float*)d_in[13];
    const float* bih_ns  = (const float*)d_in[14];
    const float* bhh_ns  = (const float*)d_in[15];
    const float* all_fc_W = (const float*)d_in[16];
    const float* all_fc_b = (const float*)d_in[17];
    const float* convW[3] = {(const float*)d_in[18], (const float*)d_in[20], (const float*)d_in[22]};
    const float* convB[3] = {(const float*)d_in[19], (const float*)d_in[21], (const float*)d_in[23]};
    const float* lnG[2] = {(const float*)d_in[24], (const float*)d_in[26]};
    const float* lnB[2] = {(const float*)d_in[25], (const float*)d_in[27]};
    const float* mp1_W = (const float*)d_in[28];
    const float* mp1_b = (const float*)d_in[29];
    const float* mp2_W = (const float*)d_in[30];
    const float* mp2_b = (const float*)d_in[31];
    float* out = (float*)d_out;
    (void)in_sizes; (void)n_in; (void)out_size;

    float *H, *cat, *bufA, *bufB, *bufC, *logits;
    cudaGetSymbolAddress((void**)&H, g_H);
    cudaGetSymbolAddress((void**)&cat, g_cat);
    cudaGetSymbolAddress((void**)&bufA, g_bufA);
    cudaGetSymbolAddress((void**)&bufB, g_bufB);
    cudaGetSymbolAddress((void**)&bufC, g_bufC);
    cudaGetSymbolAddress((void**)&logits, g_logits);

    cudaFuncSetAttribute(gi_bf16_kernel, cudaFuncAttributeMaxDynamicSharedMemorySize, GI_SMEM);
    cudaFuncSetAttribute(gru_mma_kernel, cudaFuncAttributeMaxDynamicSharedMemorySize, GRU_SMEM);

    // launch order: capture slot (idx 3) lands on gi_bf16_kernel
    wsplit_kernel<<<(NGRU * H3 * 64 + 255) / 256, 256>>>(Wih_lp, Wih_ns);
    deg_init_kernel<<<2, 256>>>();
    deg_edge_kernel<<<NEDGES / 256, 256>>>(edge);
    gi_bf16_kernel<<<dim3(480, NGRU), 256, GI_SMEM>>>(x_lp, x_ns, bih_lp, bih_ns);
    gru_mma_kernel<<<dim3(16, NGRU), 256, GRU_SMEM>>>(Whh_lp, bhh_lp, Whh_ns, bhh_ns);
    dinv_kernel<<<2, 256>>>();

    gemm_tn_kernel<<<dim3(16, 4), 256>>>(H, LPN * DD, lp_fc_W, LPN * DD, lp_fc_b,
                                         cat + 3 * NNODES * DD, DD, NNODES, DD, LPN * DD);
    build_cat_kernel<<<256, 256>>>(x_pdt, x_ref, x_def);
    gemm_tn_kernel<<<dim3(16, 4), 256>>>(cat, 5 * DD, all_fc_W, 5 * DD, all_fc_b,
                                         bufA, DD, NNODES, DD, 5 * DD);

    // conv0
    gemm_tn_kernel<<<dim3(16, 4), 256>>>(bufA, DD, convW[0], DD, nullptr, bufB, DD, NNODES, DD, DD);
    agg_init_kernel<<<256, 256>>>(bufB, convB[0], bufC);
    agg_edge_kernel<<<NEDGES * DD / 256, 256>>>(bufB, edge, bufC);
    relu_ln_kernel<<<NNODES, 128>>>(bufC, lnG[0], lnB[0], bufA);
    // conv1
    gemm_tn_kernel<<<dim3(16, 4), 256>>>(bufA, DD, convW[1], DD, nullptr, bufB, DD, NNODES, DD, DD);
    agg_init_kernel<<<256, 256>>>(bufB, convB[1], bufC);
    agg_edge_kernel<<<NEDGES * DD / 256, 256>>>(bufB, edge, bufC);
    relu_ln_kernel<<<NNODES, 128>>>(bufC, lnG[1], lnB[1], bufA);
    // conv2 -> emb straight to d_out[0:65536]
    gemm_tn_kernel<<<dim3(16, 4), 256>>>(bufA, DD, convW[2], DD, nullptr, bufB, DD, NNODES, DD, DD);
    agg_init_kernel<<<256, 256>>>(bufB, convB[2], out);
    agg_edge_kernel<<<NEDGES * DD / 256, 256>>>(bufB, edge, out);
    relu_kernel<<<256, 256>>>(out, bufA);
    // mp1, mp2
    gemm_tn_kernel<<<dim3(16, 4), 256>>>(bufA, DD, mp1_W, DD, mp1_b, bufB, DD, NNODES, DD, DD);
    gemm_tn_kernel<<<dim3(16, 1), 256>>>(bufB, DD, mp2_W, DD, mp2_b, logits, 2, NNODES, 2, DD);
    logsoftmax_kernel<<<2, 256>>>(out + NNODES * DD);
}